// round 9
// baseline (speedup 1.0000x reference)
#include <cuda_runtime.h>
#include <math.h>

#define NP 4096
#define NBLK 296
#define NEG_LOGN (-8.317766166719343f)   /* -log(4096) */
#define LOG2E 1.4426950408889634f
#define LN2   0.6931471805599453f

struct __align__(16) Scratch {
    float Cf [(size_t)NP * NP];            // 64 MB fp32 staging
    float CTf[(size_t)NP * NP];            // 64 MB fp32 staging (transpose)
    unsigned short Qxx[(size_t)NP * NP];   // 32 MB quantized
    unsigned short Qyy[(size_t)NP * NP];
    unsigned short QD [(size_t)NP * NP];
    unsigned short QDT[(size_t)NP * NP];
    float oxx[NP], sxx[NP];                // per-row offset + scale
    float oyy[NP], syy[NP];
    float oD [NP], sD [NP];
    float oDT[NP], sDT[NP];
    float xt[NP * 64], yt[NP * 64];
    float sqx[NP], sqy[NP];
    float f[2][NP], g[2][NP];
    float fin[4][NP];
};
__device__ Scratch S;

// ---------------------------------------------------------------------------
// software grid barrier (NBLK blocks, 2/SM co-resident via launch_bounds)
// ---------------------------------------------------------------------------
__device__ unsigned g_cnt;
__device__ unsigned g_gen;

__device__ __forceinline__ void gsync() {
    __threadfence();
    __syncthreads();
    if (threadIdx.x == 0) {
        volatile unsigned* vg = &g_gen;
        unsigned my = *vg;
        if (atomicAdd(&g_cnt, 1u) == NBLK - 1u) {
            g_cnt = 0u;
            __threadfence();
            *vg = my + 1u;
        } else {
            while (*vg == my) { __nanosleep(32); }
        }
    }
    __syncthreads();
}

// ---------------------------------------------------------------------------
__global__ void prep_kernel(const float* __restrict__ x, const float* __restrict__ y,
                            float* __restrict__ xt, float* __restrict__ yt,
                            float* __restrict__ sqx, float* __restrict__ sqy) {
    int p = blockIdx.x * blockDim.x + threadIdx.x;
    float sx = 0.f, sy = 0.f;
    #pragma unroll 8
    for (int c = 0; c < 64; c++) {
        float vx = x[c * NP + p];
        float vy = y[c * NP + p];
        xt[p * 64 + c] = vx;
        yt[p * 64 + c] = vy;
        sx = fmaf(vx, vx, sx);
        sy = fmaf(vy, vy, sy);
    }
    sqx[p] = sx; sqy[p] = sy;
}

// ---------------------------------------------------------------------------
// cost: C[i][j] = 0.5*(|a_i|^2 + |b_j|^2 - 2 a_i.b_j)
// ---------------------------------------------------------------------------
__global__ void cost_kernel(const float* __restrict__ A, const float* __restrict__ Bm,
                            const float* __restrict__ sqa, const float* __restrict__ sqb,
                            float* __restrict__ C) {
    __shared__ float As[16 * 128];
    __shared__ float Bs[16 * 128];
    int tid = threadIdx.x;
    int tx = tid & 15, ty = tid >> 4;
    int i0 = blockIdx.y * 128, j0 = blockIdx.x * 128;

    float acc[8][8];
    #pragma unroll
    for (int r = 0; r < 8; r++)
        #pragma unroll
        for (int c = 0; c < 8; c++) acc[r][c] = 0.f;

    for (int c0 = 0; c0 < 64; c0 += 16) {
        #pragma unroll
        for (int n = 0; n < 2; n++) {
            int idx = tid + n * 256;
            int r = idx >> 2, q = idx & 3;
            float4 va = *(const float4*)&A[(size_t)(i0 + r) * 64 + c0 + q * 4];
            As[(q * 4 + 0) * 128 + r] = va.x;
            As[(q * 4 + 1) * 128 + r] = va.y;
            As[(q * 4 + 2) * 128 + r] = va.z;
            As[(q * 4 + 3) * 128 + r] = va.w;
            float4 vb = *(const float4*)&Bm[(size_t)(j0 + r) * 64 + c0 + q * 4];
            Bs[(q * 4 + 0) * 128 + r] = vb.x;
            Bs[(q * 4 + 1) * 128 + r] = vb.y;
            Bs[(q * 4 + 2) * 128 + r] = vb.z;
            Bs[(q * 4 + 3) * 128 + r] = vb.w;
        }
        __syncthreads();
        #pragma unroll
        for (int k = 0; k < 16; k++) {
            float a[8], bb[8];
            *(float4*)&a[0]  = *(const float4*)&As[k * 128 + ty * 8];
            *(float4*)&a[4]  = *(const float4*)&As[k * 128 + ty * 8 + 4];
            *(float4*)&bb[0] = *(const float4*)&Bs[k * 128 + tx * 8];
            *(float4*)&bb[4] = *(const float4*)&Bs[k * 128 + tx * 8 + 4];
            #pragma unroll
            for (int r = 0; r < 8; r++)
                #pragma unroll
                for (int c = 0; c < 8; c++)
                    acc[r][c] = fmaf(a[r], bb[c], acc[r][c]);
        }
        __syncthreads();
    }

    float sj[8];
    #pragma unroll
    for (int c = 0; c < 8; c++) sj[c] = sqb[j0 + tx * 8 + c];

    #pragma unroll
    for (int r = 0; r < 8; r++) {
        int i = i0 + ty * 8 + r;
        float si = sqa[i];
        float o[8];
        #pragma unroll
        for (int c = 0; c < 8; c++)
            o[c] = 0.5f * (si + sj[c] - 2.f * acc[r][c]);
        float* dst = &C[(size_t)i * NP + j0 + tx * 8];
        *(float4*)&dst[0] = *(float4*)&o[0];
        *(float4*)&dst[4] = *(float4*)&o[4];
    }
}

// ---------------------------------------------------------------------------
// transpose C -> CT (32x32 smem tiles)
// ---------------------------------------------------------------------------
__global__ void transpose_kernel(const float* __restrict__ A, float* __restrict__ B) {
    __shared__ float t[32][33];
    int x = blockIdx.x * 32 + threadIdx.x;
    int y = blockIdx.y * 32 + threadIdx.y;
    #pragma unroll
    for (int j = 0; j < 32; j += 8)
        t[threadIdx.y + j][threadIdx.x] = A[(size_t)(y + j) * NP + x];
    __syncthreads();
    x = blockIdx.y * 32 + threadIdx.x;
    y = blockIdx.x * 32 + threadIdx.y;
    #pragma unroll
    for (int j = 0; j < 32; j += 8)
        B[(size_t)(y + j) * NP + x] = t[threadIdx.x][threadIdx.y + j];
}

// ---------------------------------------------------------------------------
// quantize one row: u = round((C - rmin)/scl), scl = (rmax-rmin)/65535.
// off[row] = rmin, scl[row] = scl. Block (256 threads) per row.
// ---------------------------------------------------------------------------
__global__ void __launch_bounds__(256) quant_kernel(
        const float* __restrict__ Cf, unsigned short* __restrict__ Q,
        float* __restrict__ off, float* __restrict__ scl) {
    __shared__ float rmn[256], rmx[256];
    __shared__ float s_min, s_inv, s_q;
    int row = blockIdx.x, tid = threadIdx.x;
    const float4* r4 = (const float4*)(Cf + (size_t)row * NP);
    float mn = INFINITY, mx = -INFINITY;
    float4 a[4];
    #pragma unroll
    for (int k = 0; k < 4; k++) {
        float4 v = r4[tid * 4 + k];
        a[k] = v;
        mn = fminf(mn, fminf(fminf(v.x, v.y), fminf(v.z, v.w)));
        mx = fmaxf(mx, fmaxf(fmaxf(v.x, v.y), fmaxf(v.z, v.w)));
    }
    rmn[tid] = mn; rmx[tid] = mx;
    __syncthreads();
    for (int s = 128; s; s >>= 1) {
        if (tid < s) {
            rmn[tid] = fminf(rmn[tid], rmn[tid + s]);
            rmx[tid] = fmaxf(rmx[tid], rmx[tid + s]);
        }
        __syncthreads();
    }
    if (tid == 0) {
        float lo = rmn[0], hi = rmx[0];
        float q = fmaxf((hi - lo) / 65535.0f, 1e-12f);
        off[row] = lo; scl[row] = q;
        s_min = lo; s_inv = 1.0f / q;
    }
    __syncthreads();
    float lo = s_min, qi = s_inv;
    unsigned us[16];
    #pragma unroll
    for (int k = 0; k < 4; k++) {
        us[k*4+0] = (unsigned)fminf(fmaxf(rintf((a[k].x - lo) * qi), 0.f), 65535.f);
        us[k*4+1] = (unsigned)fminf(fmaxf(rintf((a[k].y - lo) * qi), 0.f), 65535.f);
        us[k*4+2] = (unsigned)fminf(fmaxf(rintf((a[k].z - lo) * qi), 0.f), 65535.f);
        us[k*4+3] = (unsigned)fminf(fmaxf(rintf((a[k].w - lo) * qi), 0.f), 65535.f);
    }
    uint4* q4 = (uint4*)(Q + (size_t)row * NP);
    uint4 w0, w1;
    w0.x = us[0]  | (us[1]  << 16); w0.y = us[2]  | (us[3]  << 16);
    w0.z = us[4]  | (us[5]  << 16); w0.w = us[6]  | (us[7]  << 16);
    w1.x = us[8]  | (us[9]  << 16); w1.y = us[10] | (us[11] << 16);
    w1.z = us[12] | (us[13] << 16); w1.w = us[14] | (us[15] << 16);
    q4[tid * 2]     = w0;
    q4[tid * 2 + 1] = w1;
}

// ---------------------------------------------------------------------------
// u16 -> float decode (exact): (0x4B000000 | u) as float == 2^23 + u
// ---------------------------------------------------------------------------
__device__ __forceinline__ float u16lo(unsigned w) {
    return __uint_as_float(__byte_perm(w, 0x4B000000u, 0x7410)) - 8388608.0f;
}
__device__ __forceinline__ float u16hi(unsigned w) {
    return __uint_as_float(__byte_perm(w, 0x4B000000u, 0x7432)) - 8388608.0f;
}

// one 16-element chunk of the online LSE, with safe negligibility skip.
// h: float4 slots [0],[1] for first uint4, [64],[65] for second (slot+32).
__device__ __forceinline__ void chunk16q(uint4 a0, uint4 a1,
                                         const float4* __restrict__ h,
                                         float kq, float& m, float& s) {
    float4 h0 = h[0], h1 = h[1], h2 = h[64], h3 = h[65];
    float v[16];
    v[0]  = fmaf(u16lo(a0.x), kq, h0.x); v[1]  = fmaf(u16hi(a0.x), kq, h0.y);
    v[2]  = fmaf(u16lo(a0.y), kq, h0.z); v[3]  = fmaf(u16hi(a0.y), kq, h0.w);
    v[4]  = fmaf(u16lo(a0.z), kq, h1.x); v[5]  = fmaf(u16hi(a0.z), kq, h1.y);
    v[6]  = fmaf(u16lo(a0.w), kq, h1.z); v[7]  = fmaf(u16hi(a0.w), kq, h1.w);
    v[8]  = fmaf(u16lo(a1.x), kq, h2.x); v[9]  = fmaf(u16hi(a1.x), kq, h2.y);
    v[10] = fmaf(u16lo(a1.y), kq, h2.z); v[11] = fmaf(u16hi(a1.y), kq, h2.w);
    v[12] = fmaf(u16lo(a1.z), kq, h3.x); v[13] = fmaf(u16hi(a1.z), kq, h3.y);
    v[14] = fmaf(u16lo(a1.w), kq, h3.z); v[15] = fmaf(u16hi(a1.w), kq, h3.w);
    float cm = v[0];
    #pragma unroll
    for (int t = 1; t < 16; t++) cm = fmaxf(cm, v[t]);
    // contribution < 16 * 2^-40 relative to running max -> below fp32 ulp
    if (__all_sync(0xffffffffu, cm < m - 40.0f)) return;
    float cs = 0.f;
    #pragma unroll
    for (int t = 0; t < 16; t++) cs += exp2f(v[t] - cm);
    float nm = fmaxf(m, cm);
    s = s * exp2f(m - nm) + cs * exp2f(cm - nm);
    m = nm;
}

// dual-stream LSE over quantized rows (both L2-resident, 64 MB total)
__device__ __forceinline__ float2 row_lse_dual_q(
        const uint4* __restrict__ QA4, const uint4* __restrict__ QB4,
        const float4* __restrict__ HA, const float4* __restrict__ HB,
        float kqA, float kqB, int lane) {
    float mA = -INFINITY, sA = 0.f;
    float mB = -INFINITY, sB = 0.f;
    #pragma unroll
    for (int seg = 0; seg < 8; seg++) {
        int sa = seg * 64 + lane;
        uint4 a0 = QA4[sa], a1 = QA4[sa + 32];
        uint4 b0 = QB4[sa], b1 = QB4[sa + 32];
        chunk16q(a0, a1, HA + sa * 2, kqA, mA, sA);
        chunk16q(b0, b1, HB + sa * 2, kqB, mB, sB);
    }
    #pragma unroll
    for (int off = 16; off; off >>= 1) {
        float om = __shfl_xor_sync(0xffffffffu, mA, off);
        float os = __shfl_xor_sync(0xffffffffu, sA, off);
        float nm = fmaxf(mA, om);
        sA = sA * exp2f(mA - nm) + os * exp2f(om - nm);
        mA = nm;
        float om2 = __shfl_xor_sync(0xffffffffu, mB, off);
        float os2 = __shfl_xor_sync(0xffffffffu, sB, off);
        float nm2 = fmaxf(mB, om2);
        sB = sB * exp2f(mB - nm2) + os2 * exp2f(om2 - nm2);
        mB = nm2;
    }
    return make_float2(mA + log2f(sA), mB + log2f(sB));
}

__device__ __forceinline__ void init_eps(float* sh_eps, int tid) {
    if (tid < 56) {
        double e = (tid < 55)
            ? exp(5.545177444479562 - 0.21072103131565253 * (double)tid)
            : 0.0025;
        sh_eps[tid] = (float)e;
    }
}

__device__ __forceinline__ void fill_bias(float* sh, const float* pot,
                                          float inv_e, int tid) {
    const float4* p4 = (const float4*)pot;
    float4* s4 = (float4*)sh;
    #pragma unroll
    for (int q = 0; q < 2; q++) {
        int j = tid + q * 512;
        float4 v = __ldcg(p4 + j);
        float4 o;
        o.x = fmaf(v.x, inv_e, NEG_LOGN) * LOG2E;
        o.y = fmaf(v.y, inv_e, NEG_LOGN) * LOG2E;
        o.z = fmaf(v.z, inv_e, NEG_LOGN) * LOG2E;
        o.w = fmaf(v.w, inv_e, NEG_LOGN) * LOG2E;
        s4[j] = o;
    }
}

// ---------------------------------------------------------------------------
// dual annealing phase on quantized matrices.
//   stream A: row of QA (offset offA, scale sclA), bias bA[cur] -> update uA
//   stream B: row of QB likewise.
// true val = off[row] - eps*ln2*lse_u   (row offset re-added exactly)
// ---------------------------------------------------------------------------
__global__ void __launch_bounds__(512, 2) dual_phase_kernel(
        const unsigned short* __restrict__ QA, const unsigned short* __restrict__ QB,
        const float* __restrict__ offA, const float* __restrict__ sclA,
        const float* __restrict__ offB, const float* __restrict__ sclB,
        float* __restrict__ bA0, float* __restrict__ bA1,
        float* __restrict__ uA0, float* __restrict__ uA1,
        float* __restrict__ bB0, float* __restrict__ bB1,
        float* __restrict__ uB0, float* __restrict__ uB1,
        float* __restrict__ outA, float* __restrict__ outB) {
    __shared__ __align__(16) float shA[NP];
    __shared__ __align__(16) float shB[NP];
    __shared__ float sh_eps[56];
    int tid = threadIdx.x, lane = tid & 31, warp = tid >> 5;
    int row = warp * NBLK + (int)blockIdx.x;
    bool active = row < NP;
    int prow = active ? row : 0;
    init_eps(sh_eps, tid);
    const uint4* QA4 = (const uint4*)(QA + (size_t)prow * NP);
    const uint4* QB4 = (const uint4*)(QB + (size_t)prow * NP);
    float oA = offA[prow], qA = sclA[prow];
    float oB = offB[prow], qB = sclB[prow];
    float* bA[2] = { bA0, bA1 };
    float* uA[2] = { uA0, uA1 };
    float* bB[2] = { bB0, bB1 };
    float* uB[2] = { uB0, uB1 };
    int cur = 0;
    __syncthreads();

    for (int t = 0; t <= 57; t++) {
        int ke = (t == 0) ? 0 : (t == 57 ? 55 : t - 1);
        float e = sh_eps[ke];
        float inv_e = 1.f / e;
        float kqA = -qA * inv_e * LOG2E;
        float kqB = -qB * inv_e * LOG2E;
        // quantized arg needs the per-row offset folded into the bias constant:
        // true log2-arg = h[j] - (o + u*q)/e*log2e ; the -o/e*log2e part is a
        // row constant, re-added after the LSE (val = o - e*ln2*lse_u ... plus
        // careful: bias term must NOT include it). h[j] built as before.
        if (t == 0) {
            for (int j = tid; j < NP; j += 512) {
                shA[j] = NEG_LOGN * LOG2E;
                shB[j] = NEG_LOGN * LOG2E;
            }
        } else {
            fill_bias(shA, bA[cur], inv_e, tid);
            fill_bias(shB, bB[cur], inv_e, tid);
        }
        __syncthreads();

        float2 ls = row_lse_dual_q(QA4, QB4, (const float4*)shA,
                                   (const float4*)shB, kqA, kqB, lane);

        if (lane == 0 && active) {
            float vA = oA - e * LN2 * ls.x;
            float vB = oB - e * LN2 * ls.y;
            if (t == 57) {
                outA[row] = vA;
                outB[row] = vB;
            } else if (t == 0) {
                __stcg(&uA[1][row], vA);
                __stcg(&uB[1][row], vB);
            } else {
                __stcg(&uA[cur ^ 1][row],
                       0.5f * __ldcg(&uA[cur][row]) + 0.5f * vA);
                __stcg(&uB[cur ^ 1][row],
                       0.5f * __ldcg(&uB[cur][row]) + 0.5f * vB);
            }
        }
        if (t == 0) cur = 1; else if (t < 57) cur ^= 1;
        if (t < 57) gsync();
    }
}

// ---------------------------------------------------------------------------
__global__ void loss_reduce(const float* __restrict__ fin, float* __restrict__ out, int first) {
    __shared__ float red[256];
    int tid = threadIdx.x;
    float a = 0.f;
    for (int j = tid; j < NP; j += 256)
        a += (fin[2 * NP + j] - fin[0 * NP + j]) + (fin[3 * NP + j] - fin[1 * NP + j]);
    red[tid] = a;
    __syncthreads();
    for (int sft = 128; sft; sft >>= 1) {
        if (tid < sft) red[tid] += red[tid + sft];
        __syncthreads();
    }
    if (tid == 0) {
        float v = red[0] * (1.0f / NP) * 0.25f;
        if (first) *out = v; else *out += v;
    }
}

// ---------------------------------------------------------------------------
extern "C" void kernel_launch(void* const* d_in, const int* in_sizes, int n_in,
                              void* d_out, int out_size) {
    (void)in_sizes; (void)n_in; (void)out_size;
    const float* x = (const float*)d_in[0];
    const float* y = (const float*)d_in[1];
    float* out = (float*)d_out;

    Scratch* sp = nullptr;
    cudaGetSymbolAddress((void**)&sp, S);
    float* Cf  = sp->Cf;  float* CTf = sp->CTf;
    float* xt  = sp->xt;  float* yt  = sp->yt;
    float* sqx = sp->sqx; float* sqy = sp->sqy;
    float* f0 = sp->f[0]; float* f1 = sp->f[1];
    float* g0 = sp->g[0]; float* g1 = sp->g[1];
    float* fin = (float*)sp->fin;

    for (int b = 0; b < 4; b++) {
        const float* xb = x + (size_t)b * 64 * NP;
        const float* yb = y + (size_t)b * 64 * NP;
        prep_kernel<<<16, 256>>>(xb, yb, xt, yt, sqx, sqy);

        cost_kernel<<<dim3(32, 32), 256>>>(xt, xt, sqx, sqx, Cf);
        quant_kernel<<<NP, 256>>>(Cf, sp->Qxx, sp->oxx, sp->sxx);

        cost_kernel<<<dim3(32, 32), 256>>>(yt, yt, sqy, sqy, Cf);
        quant_kernel<<<NP, 256>>>(Cf, sp->Qyy, sp->oyy, sp->syy);

        cost_kernel<<<dim3(32, 32), 256>>>(xt, yt, sqx, sqy, Cf);
        transpose_kernel<<<dim3(128, 128), dim3(32, 8)>>>(Cf, CTf);
        quant_kernel<<<NP, 256>>>(Cf,  sp->QD,  sp->oD,  sp->sD);
        quant_kernel<<<NP, 256>>>(CTf, sp->QDT, sp->oDT, sp->sDT);

        // fused xx+yy phase (self-coupled streams)
        dual_phase_kernel<<<NBLK, 512>>>(sp->Qxx, sp->Qyy,
                                         sp->oxx, sp->sxx, sp->oyy, sp->syy,
                                         f0, f1, f0, f1,
                                         g0, g1, g0, g1,
                                         fin + 0 * NP, fin + 1 * NP);
        // xy phase (cross-coupled: A biases on g updates f; B biases on f updates g)
        dual_phase_kernel<<<NBLK, 512>>>(sp->QD, sp->QDT,
                                         sp->oD, sp->sD, sp->oDT, sp->sDT,
                                         g0, g1, f0, f1,
                                         f0, f1, g0, g1,
                                         fin + 2 * NP, fin + 3 * NP);

        loss_reduce<<<1, 256>>>(fin, out, b == 0 ? 1 : 0);
    }
}

// round 10
// speedup vs baseline: 1.0013x; 1.0013x over previous
#include <cuda_runtime.h>
#include <math.h>

#define NP 4096
#define NBLK 296
#define NEG_LOGN (-8.317766166719343f)   /* -log(4096) */
#define LOG2E 1.4426950408889634f
#define LN2   0.6931471805599453f

struct __align__(16) Scratch {
    float Cf [(size_t)NP * NP];            // 64 MB fp32 staging
    float CTf[(size_t)NP * NP];            // 64 MB fp32 staging (transpose)
    unsigned short Qxx[(size_t)NP * NP];   // 32 MB quantized
    unsigned short Qyy[(size_t)NP * NP];
    unsigned short QD [(size_t)NP * NP];
    unsigned short QDT[(size_t)NP * NP];
    float oxx[NP], sxx[NP];                // per-row offset + scale
    float oyy[NP], syy[NP];
    float oD [NP], sD [NP];
    float oDT[NP], sDT[NP];
    float xt[NP * 64], yt[NP * 64];
    float sqx[NP], sqy[NP];
    float f[2][NP], g[2][NP];
    float fin[4][NP];
};
__device__ Scratch S;

// ---------------------------------------------------------------------------
// software grid barrier (NBLK blocks, 2/SM co-resident via launch_bounds)
// ---------------------------------------------------------------------------
__device__ unsigned g_cnt;
__device__ unsigned g_gen;

__device__ __forceinline__ void gsync() {
    __threadfence();
    __syncthreads();
    if (threadIdx.x == 0) {
        volatile unsigned* vg = &g_gen;
        unsigned my = *vg;
        if (atomicAdd(&g_cnt, 1u) == NBLK - 1u) {
            g_cnt = 0u;
            __threadfence();
            *vg = my + 1u;
        } else {
            while (*vg == my) { __nanosleep(32); }
        }
    }
    __syncthreads();
}

// ---------------------------------------------------------------------------
__global__ void prep_kernel(const float* __restrict__ x, const float* __restrict__ y,
                            float* __restrict__ xt, float* __restrict__ yt,
                            float* __restrict__ sqx, float* __restrict__ sqy) {
    int p = blockIdx.x * blockDim.x + threadIdx.x;
    float sx = 0.f, sy = 0.f;
    #pragma unroll 8
    for (int c = 0; c < 64; c++) {
        float vx = x[c * NP + p];
        float vy = y[c * NP + p];
        xt[p * 64 + c] = vx;
        yt[p * 64 + c] = vy;
        sx = fmaf(vx, vx, sx);
        sy = fmaf(vy, vy, sy);
    }
    sqx[p] = sx; sqy[p] = sy;
}

// ---------------------------------------------------------------------------
// cost: C[i][j] = 0.5*(|a_i|^2 + |b_j|^2 - 2 a_i.b_j)
// ---------------------------------------------------------------------------
__global__ void cost_kernel(const float* __restrict__ A, const float* __restrict__ Bm,
                            const float* __restrict__ sqa, const float* __restrict__ sqb,
                            float* __restrict__ C) {
    __shared__ float As[16 * 128];
    __shared__ float Bs[16 * 128];
    int tid = threadIdx.x;
    int tx = tid & 15, ty = tid >> 4;
    int i0 = blockIdx.y * 128, j0 = blockIdx.x * 128;

    float acc[8][8];
    #pragma unroll
    for (int r = 0; r < 8; r++)
        #pragma unroll
        for (int c = 0; c < 8; c++) acc[r][c] = 0.f;

    for (int c0 = 0; c0 < 64; c0 += 16) {
        #pragma unroll
        for (int n = 0; n < 2; n++) {
            int idx = tid + n * 256;
            int r = idx >> 2, q = idx & 3;
            float4 va = *(const float4*)&A[(size_t)(i0 + r) * 64 + c0 + q * 4];
            As[(q * 4 + 0) * 128 + r] = va.x;
            As[(q * 4 + 1) * 128 + r] = va.y;
            As[(q * 4 + 2) * 128 + r] = va.z;
            As[(q * 4 + 3) * 128 + r] = va.w;
            float4 vb = *(const float4*)&Bm[(size_t)(j0 + r) * 64 + c0 + q * 4];
            Bs[(q * 4 + 0) * 128 + r] = vb.x;
            Bs[(q * 4 + 1) * 128 + r] = vb.y;
            Bs[(q * 4 + 2) * 128 + r] = vb.z;
            Bs[(q * 4 + 3) * 128 + r] = vb.w;
        }
        __syncthreads();
        #pragma unroll
        for (int k = 0; k < 16; k++) {
            float a[8], bb[8];
            *(float4*)&a[0]  = *(const float4*)&As[k * 128 + ty * 8];
            *(float4*)&a[4]  = *(const float4*)&As[k * 128 + ty * 8 + 4];
            *(float4*)&bb[0] = *(const float4*)&Bs[k * 128 + tx * 8];
            *(float4*)&bb[4] = *(const float4*)&Bs[k * 128 + tx * 8 + 4];
            #pragma unroll
            for (int r = 0; r < 8; r++)
                #pragma unroll
                for (int c = 0; c < 8; c++)
                    acc[r][c] = fmaf(a[r], bb[c], acc[r][c]);
        }
        __syncthreads();
    }

    float sj[8];
    #pragma unroll
    for (int c = 0; c < 8; c++) sj[c] = sqb[j0 + tx * 8 + c];

    #pragma unroll
    for (int r = 0; r < 8; r++) {
        int i = i0 + ty * 8 + r;
        float si = sqa[i];
        float o[8];
        #pragma unroll
        for (int c = 0; c < 8; c++)
            o[c] = 0.5f * (si + sj[c] - 2.f * acc[r][c]);
        float* dst = &C[(size_t)i * NP + j0 + tx * 8];
        *(float4*)&dst[0] = *(float4*)&o[0];
        *(float4*)&dst[4] = *(float4*)&o[4];
    }
}

// ---------------------------------------------------------------------------
// transpose C -> CT (32x32 smem tiles)
// ---------------------------------------------------------------------------
__global__ void transpose_kernel(const float* __restrict__ A, float* __restrict__ B) {
    __shared__ float t[32][33];
    int x = blockIdx.x * 32 + threadIdx.x;
    int y = blockIdx.y * 32 + threadIdx.y;
    #pragma unroll
    for (int j = 0; j < 32; j += 8)
        t[threadIdx.y + j][threadIdx.x] = A[(size_t)(y + j) * NP + x];
    __syncthreads();
    x = blockIdx.y * 32 + threadIdx.x;
    y = blockIdx.x * 32 + threadIdx.y;
    #pragma unroll
    for (int j = 0; j < 32; j += 8)
        B[(size_t)(y + j) * NP + x] = t[threadIdx.x][threadIdx.y + j];
}

// ---------------------------------------------------------------------------
// quantize one row: u = round((C - rmin)/scl), scl = (rmax-rmin)/65535.
// ---------------------------------------------------------------------------
__global__ void __launch_bounds__(256) quant_kernel(
        const float* __restrict__ Cf, unsigned short* __restrict__ Q,
        float* __restrict__ off, float* __restrict__ scl) {
    __shared__ float rmn[256], rmx[256];
    __shared__ float s_min, s_inv;
    int row = blockIdx.x, tid = threadIdx.x;
    const float4* r4 = (const float4*)(Cf + (size_t)row * NP);
    float mn = INFINITY, mx = -INFINITY;
    float4 a[4];
    #pragma unroll
    for (int k = 0; k < 4; k++) {
        float4 v = r4[tid * 4 + k];
        a[k] = v;
        mn = fminf(mn, fminf(fminf(v.x, v.y), fminf(v.z, v.w)));
        mx = fmaxf(mx, fmaxf(fmaxf(v.x, v.y), fmaxf(v.z, v.w)));
    }
    rmn[tid] = mn; rmx[tid] = mx;
    __syncthreads();
    for (int s = 128; s; s >>= 1) {
        if (tid < s) {
            rmn[tid] = fminf(rmn[tid], rmn[tid + s]);
            rmx[tid] = fmaxf(rmx[tid], rmx[tid + s]);
        }
        __syncthreads();
    }
    if (tid == 0) {
        float lo = rmn[0], hi = rmx[0];
        float q = fmaxf((hi - lo) / 65535.0f, 1e-12f);
        off[row] = lo; scl[row] = q;
        s_min = lo; s_inv = 1.0f / q;
    }
    __syncthreads();
    float lo = s_min, qi = s_inv;
    unsigned us[16];
    #pragma unroll
    for (int k = 0; k < 4; k++) {
        us[k*4+0] = (unsigned)fminf(fmaxf(rintf((a[k].x - lo) * qi), 0.f), 65535.f);
        us[k*4+1] = (unsigned)fminf(fmaxf(rintf((a[k].y - lo) * qi), 0.f), 65535.f);
        us[k*4+2] = (unsigned)fminf(fmaxf(rintf((a[k].z - lo) * qi), 0.f), 65535.f);
        us[k*4+3] = (unsigned)fminf(fmaxf(rintf((a[k].w - lo) * qi), 0.f), 65535.f);
    }
    uint4* q4 = (uint4*)(Q + (size_t)row * NP);
    uint4 w0, w1;
    w0.x = us[0]  | (us[1]  << 16); w0.y = us[2]  | (us[3]  << 16);
    w0.z = us[4]  | (us[5]  << 16); w0.w = us[6]  | (us[7]  << 16);
    w1.x = us[8]  | (us[9]  << 16); w1.y = us[10] | (us[11] << 16);
    w1.z = us[12] | (us[13] << 16); w1.w = us[14] | (us[15] << 16);
    q4[tid * 2]     = w0;
    q4[tid * 2 + 1] = w1;
}

// ---------------------------------------------------------------------------
// u16 -> float decode (exact): (0x4B000000 | u) as float == 2^23 + u
// ---------------------------------------------------------------------------
__device__ __forceinline__ float u16lo(unsigned w) {
    return __uint_as_float(__byte_perm(w, 0x4B000000u, 0x7410)) - 8388608.0f;
}
__device__ __forceinline__ float u16hi(unsigned w) {
    return __uint_as_float(__byte_perm(w, 0x4B000000u, 0x7432)) - 8388608.0f;
}

// one 16-element chunk of the online LSE, with safe negligibility skip.
__device__ __forceinline__ void chunk16q(uint4 a0, uint4 a1,
                                         const float4* __restrict__ h,
                                         float kq, float& m, float& s) {
    float4 h0 = h[0], h1 = h[1], h2 = h[64], h3 = h[65];
    float v[16];
    v[0]  = fmaf(u16lo(a0.x), kq, h0.x); v[1]  = fmaf(u16hi(a0.x), kq, h0.y);
    v[2]  = fmaf(u16lo(a0.y), kq, h0.z); v[3]  = fmaf(u16hi(a0.y), kq, h0.w);
    v[4]  = fmaf(u16lo(a0.z), kq, h1.x); v[5]  = fmaf(u16hi(a0.z), kq, h1.y);
    v[6]  = fmaf(u16lo(a0.w), kq, h1.z); v[7]  = fmaf(u16hi(a0.w), kq, h1.w);
    v[8]  = fmaf(u16lo(a1.x), kq, h2.x); v[9]  = fmaf(u16hi(a1.x), kq, h2.y);
    v[10] = fmaf(u16lo(a1.y), kq, h2.z); v[11] = fmaf(u16hi(a1.y), kq, h2.w);
    v[12] = fmaf(u16lo(a1.z), kq, h3.x); v[13] = fmaf(u16hi(a1.z), kq, h3.y);
    v[14] = fmaf(u16lo(a1.w), kq, h3.z); v[15] = fmaf(u16hi(a1.w), kq, h3.w);
    float cm = v[0];
    #pragma unroll
    for (int t = 1; t < 16; t++) cm = fmaxf(cm, v[t]);
    // contribution < 16 * 2^-40 relative to running max -> below fp32 ulp
    if (__all_sync(0xffffffffu, cm < m - 40.0f)) return;
    float cs = 0.f;
    #pragma unroll
    for (int t = 0; t < 16; t++) cs += exp2f(v[t] - cm);
    float nm = fmaxf(m, cm);
    s = s * exp2f(m - nm) + cs * exp2f(cm - nm);
    m = nm;
}

// dual-stream LSE over quantized rows.
// Stream A: default (.ca) loads — 32 rows/SM = 256KB ~fits L1, persists
//           across iterations (L1 kept within a launch) -> L1 hits.
// Stream B: __ldcg (L2-only, no L1 allocation) -> does not thrash A's L1.
__device__ __forceinline__ float2 row_lse_dual_q(
        const uint4* __restrict__ QA4, const uint4* __restrict__ QB4,
        const float4* __restrict__ HA, const float4* __restrict__ HB,
        float kqA, float kqB, int lane) {
    float mA = -INFINITY, sA = 0.f;
    float mB = -INFINITY, sB = 0.f;
    #pragma unroll
    for (int seg = 0; seg < 8; seg++) {
        int sa = seg * 64 + lane;
        uint4 a0 = QA4[sa], a1 = QA4[sa + 32];
        uint4 b0 = __ldcg(QB4 + sa), b1 = __ldcg(QB4 + sa + 32);
        chunk16q(a0, a1, HA + sa * 2, kqA, mA, sA);
        chunk16q(b0, b1, HB + sa * 2, kqB, mB, sB);
    }
    #pragma unroll
    for (int off = 16; off; off >>= 1) {
        float om = __shfl_xor_sync(0xffffffffu, mA, off);
        float os = __shfl_xor_sync(0xffffffffu, sA, off);
        float nm = fmaxf(mA, om);
        sA = sA * exp2f(mA - nm) + os * exp2f(om - nm);
        mA = nm;
        float om2 = __shfl_xor_sync(0xffffffffu, mB, off);
        float os2 = __shfl_xor_sync(0xffffffffu, sB, off);
        float nm2 = fmaxf(mB, om2);
        sB = sB * exp2f(mB - nm2) + os2 * exp2f(om2 - nm2);
        mB = nm2;
    }
    return make_float2(mA + log2f(sA), mB + log2f(sB));
}

__device__ __forceinline__ void init_eps(float* sh_eps, int tid) {
    if (tid < 56) {
        double e = (tid < 55)
            ? exp(5.545177444479562 - 0.21072103131565253 * (double)tid)
            : 0.0025;
        sh_eps[tid] = (float)e;
    }
}

__device__ __forceinline__ void fill_bias(float* sh, const float* pot,
                                          float inv_e, int tid) {
    const float4* p4 = (const float4*)pot;
    float4* s4 = (float4*)sh;
    #pragma unroll
    for (int q = 0; q < 2; q++) {
        int j = tid + q * 512;
        float4 v = __ldcg(p4 + j);
        float4 o;
        o.x = fmaf(v.x, inv_e, NEG_LOGN) * LOG2E;
        o.y = fmaf(v.y, inv_e, NEG_LOGN) * LOG2E;
        o.z = fmaf(v.z, inv_e, NEG_LOGN) * LOG2E;
        o.w = fmaf(v.w, inv_e, NEG_LOGN) * LOG2E;
        s4[j] = o;
    }
}

// ---------------------------------------------------------------------------
// dual annealing phase on quantized matrices (A: L1-resident, B: L2 stream)
// true val = off[row] - eps*ln2*lse_u   (row offset re-added exactly)
// ---------------------------------------------------------------------------
__global__ void __launch_bounds__(512, 2) dual_phase_kernel(
        const unsigned short* __restrict__ QA, const unsigned short* __restrict__ QB,
        const float* __restrict__ offA, const float* __restrict__ sclA,
        const float* __restrict__ offB, const float* __restrict__ sclB,
        float* __restrict__ bA0, float* __restrict__ bA1,
        float* __restrict__ uA0, float* __restrict__ uA1,
        float* __restrict__ bB0, float* __restrict__ bB1,
        float* __restrict__ uB0, float* __restrict__ uB1,
        float* __restrict__ outA, float* __restrict__ outB) {
    __shared__ __align__(16) float shA[NP];
    __shared__ __align__(16) float shB[NP];
    __shared__ float sh_eps[56];
    int tid = threadIdx.x, lane = tid & 31, warp = tid >> 5;
    int row = warp * NBLK + (int)blockIdx.x;
    bool active = row < NP;
    int prow = active ? row : 0;
    init_eps(sh_eps, tid);
    const uint4* QA4 = (const uint4*)(QA + (size_t)prow * NP);
    const uint4* QB4 = (const uint4*)(QB + (size_t)prow * NP);
    float oA = offA[prow], qA = sclA[prow];
    float oB = offB[prow], qB = sclB[prow];
    float* bA[2] = { bA0, bA1 };
    float* uA[2] = { uA0, uA1 };
    float* bB[2] = { bB0, bB1 };
    float* uB[2] = { uB0, uB1 };
    int cur = 0;
    __syncthreads();

    for (int t = 0; t <= 57; t++) {
        int ke = (t == 0) ? 0 : (t == 57 ? 55 : t - 1);
        float e = sh_eps[ke];
        float inv_e = 1.f / e;
        float kqA = -qA * inv_e * LOG2E;
        float kqB = -qB * inv_e * LOG2E;

        if (t == 0) {
            for (int j = tid; j < NP; j += 512) {
                shA[j] = NEG_LOGN * LOG2E;
                shB[j] = NEG_LOGN * LOG2E;
            }
        } else {
            fill_bias(shA, bA[cur], inv_e, tid);
            fill_bias(shB, bB[cur], inv_e, tid);
        }
        __syncthreads();

        float2 ls = row_lse_dual_q(QA4, QB4, (const float4*)shA,
                                   (const float4*)shB, kqA, kqB, lane);

        if (lane == 0 && active) {
            float vA = oA - e * LN2 * ls.x;
            float vB = oB - e * LN2 * ls.y;
            if (t == 57) {
                outA[row] = vA;
                outB[row] = vB;
            } else if (t == 0) {
                __stcg(&uA[1][row], vA);
                __stcg(&uB[1][row], vB);
            } else {
                __stcg(&uA[cur ^ 1][row],
                       0.5f * __ldcg(&uA[cur][row]) + 0.5f * vA);
                __stcg(&uB[cur ^ 1][row],
                       0.5f * __ldcg(&uB[cur][row]) + 0.5f * vB);
            }
        }
        if (t == 0) cur = 1; else if (t < 57) cur ^= 1;
        if (t < 57) gsync();
    }
}

// ---------------------------------------------------------------------------
__global__ void loss_reduce(const float* __restrict__ fin, float* __restrict__ out, int first) {
    __shared__ float red[256];
    int tid = threadIdx.x;
    float a = 0.f;
    for (int j = tid; j < NP; j += 256)
        a += (fin[2 * NP + j] - fin[0 * NP + j]) + (fin[3 * NP + j] - fin[1 * NP + j]);
    red[tid] = a;
    __syncthreads();
    for (int sft = 128; sft; sft >>= 1) {
        if (tid < sft) red[tid] += red[tid + sft];
        __syncthreads();
    }
    if (tid == 0) {
        float v = red[0] * (1.0f / NP) * 0.25f;
        if (first) *out = v; else *out += v;
    }
}

// ---------------------------------------------------------------------------
extern "C" void kernel_launch(void* const* d_in, const int* in_sizes, int n_in,
                              void* d_out, int out_size) {
    (void)in_sizes; (void)n_in; (void)out_size;
    const float* x = (const float*)d_in[0];
    const float* y = (const float*)d_in[1];
    float* out = (float*)d_out;

    Scratch* sp = nullptr;
    cudaGetSymbolAddress((void**)&sp, S);
    float* Cf  = sp->Cf;  float* CTf = sp->CTf;
    float* xt  = sp->xt;  float* yt  = sp->yt;
    float* sqx = sp->sqx; float* sqy = sp->sqy;
    float* f0 = sp->f[0]; float* f1 = sp->f[1];
    float* g0 = sp->g[0]; float* g1 = sp->g[1];
    float* fin = (float*)sp->fin;

    for (int b = 0; b < 4; b++) {
        const float* xb = x + (size_t)b * 64 * NP;
        const float* yb = y + (size_t)b * 64 * NP;

        // Launch order makes global launch #6 (batch 0) = dual_phase_kernel,
        // so ncu -s 5 -c 1 finally profiles the phase kernel.
        prep_kernel<<<16, 256>>>(xb, yb, xt, yt, sqx, sqy);            // 1
        cost_kernel<<<dim3(32, 32), 256>>>(xt, xt, sqx, sqx, Cf);      // 2
        quant_kernel<<<NP, 256>>>(Cf, sp->Qxx, sp->oxx, sp->sxx);      // 3
        cost_kernel<<<dim3(32, 32), 256>>>(yt, yt, sqy, sqy, Cf);      // 4
        quant_kernel<<<NP, 256>>>(Cf, sp->Qyy, sp->oyy, sp->syy);      // 5

        // fused xx+yy phase (self-coupled streams)                    // 6
        dual_phase_kernel<<<NBLK, 512>>>(sp->Qxx, sp->Qyy,
                                         sp->oxx, sp->sxx, sp->oyy, sp->syy,
                                         f0, f1, f0, f1,
                                         g0, g1, g0, g1,
                                         fin + 0 * NP, fin + 1 * NP);

        cost_kernel<<<dim3(32, 32), 256>>>(xt, yt, sqx, sqy, Cf);
        transpose_kernel<<<dim3(128, 128), dim3(32, 8)>>>(Cf, CTf);
        quant_kernel<<<NP, 256>>>(Cf,  sp->QD,  sp->oD,  sp->sD);
        quant_kernel<<<NP, 256>>>(CTf, sp->QDT, sp->oDT, sp->sDT);

        // xy phase (cross-coupled)
        dual_phase_kernel<<<NBLK, 512>>>(sp->QD, sp->QDT,
                                         sp->oD, sp->sD, sp->oDT, sp->sDT,
                                         g0, g1, f0, f1,
                                         f0, f1, g0, g1,
                                         fin + 2 * NP, fin + 3 * NP);

        loss_reduce<<<1, 256>>>(fin, out, b == 0 ? 1 : 0);
    }
}

// round 11
// speedup vs baseline: 1.1166x; 1.1152x over previous
#include <cuda_runtime.h>
#include <math.h>

#define NP 4096
#define NBLK 296
#define NEG_LOGN (-8.317766166719343f)   /* -log(4096) */
#define LOG2E 1.4426950408889634f
#define LN2   0.6931471805599453f

struct __align__(16) Scratch {
    float Cf [(size_t)NP * NP];            // 64 MB fp32 staging
    float CTf[(size_t)NP * NP];            // 64 MB fp32 staging (transpose)
    unsigned short Qxx[(size_t)NP * NP];   // 32 MB quantized
    unsigned short Qyy[(size_t)NP * NP];
    unsigned short QD [(size_t)NP * NP];
    unsigned short QDT[(size_t)NP * NP];
    float oxx[NP], sxx[NP];                // per-row offset + scale
    float oyy[NP], syy[NP];
    float oD [NP], sD [NP];
    float oDT[NP], sDT[NP];
    float xt[NP * 64], yt[NP * 64];
    float sqx[NP], sqy[NP];
    float f[2][NP], g[2][NP];
    float fin[4][NP];
};
__device__ Scratch S;

// single-instruction MUFU ops (exp2f/log2f libm calls expand to multi-instr
// sequences without fast-math; these are guaranteed 1x MUFU)
__device__ __forceinline__ float ex2(float x) {
    float y;
    asm("ex2.approx.ftz.f32 %0, %1;" : "=f"(y) : "f"(x));
    return y;
}
__device__ __forceinline__ float lg2(float x) {
    float y;
    asm("lg2.approx.f32 %0, %1;" : "=f"(y) : "f"(x));
    return y;
}

// ---------------------------------------------------------------------------
// software grid barrier (NBLK blocks, 2/SM co-resident via launch_bounds)
// ---------------------------------------------------------------------------
__device__ unsigned g_cnt;
__device__ unsigned g_gen;

__device__ __forceinline__ void gsync() {
    __threadfence();
    __syncthreads();
    if (threadIdx.x == 0) {
        volatile unsigned* vg = &g_gen;
        unsigned my = *vg;
        if (atomicAdd(&g_cnt, 1u) == NBLK - 1u) {
            g_cnt = 0u;
            __threadfence();
            *vg = my + 1u;
        } else {
            while (*vg == my) { __nanosleep(32); }
        }
    }
    __syncthreads();
}

// ---------------------------------------------------------------------------
__global__ void prep_kernel(const float* __restrict__ x, const float* __restrict__ y,
                            float* __restrict__ xt, float* __restrict__ yt,
                            float* __restrict__ sqx, float* __restrict__ sqy) {
    int p = blockIdx.x * blockDim.x + threadIdx.x;
    float sx = 0.f, sy = 0.f;
    #pragma unroll 8
    for (int c = 0; c < 64; c++) {
        float vx = x[c * NP + p];
        float vy = y[c * NP + p];
        xt[p * 64 + c] = vx;
        yt[p * 64 + c] = vy;
        sx = fmaf(vx, vx, sx);
        sy = fmaf(vy, vy, sy);
    }
    sqx[p] = sx; sqy[p] = sy;
}

// ---------------------------------------------------------------------------
// cost: C[i][j] = 0.5*(|a_i|^2 + |b_j|^2 - 2 a_i.b_j)
// ---------------------------------------------------------------------------
__global__ void cost_kernel(const float* __restrict__ A, const float* __restrict__ Bm,
                            const float* __restrict__ sqa, const float* __restrict__ sqb,
                            float* __restrict__ C) {
    __shared__ float As[16 * 128];
    __shared__ float Bs[16 * 128];
    int tid = threadIdx.x;
    int tx = tid & 15, ty = tid >> 4;
    int i0 = blockIdx.y * 128, j0 = blockIdx.x * 128;

    float acc[8][8];
    #pragma unroll
    for (int r = 0; r < 8; r++)
        #pragma unroll
        for (int c = 0; c < 8; c++) acc[r][c] = 0.f;

    for (int c0 = 0; c0 < 64; c0 += 16) {
        #pragma unroll
        for (int n = 0; n < 2; n++) {
            int idx = tid + n * 256;
            int r = idx >> 2, q = idx & 3;
            float4 va = *(const float4*)&A[(size_t)(i0 + r) * 64 + c0 + q * 4];
            As[(q * 4 + 0) * 128 + r] = va.x;
            As[(q * 4 + 1) * 128 + r] = va.y;
            As[(q * 4 + 2) * 128 + r] = va.z;
            As[(q * 4 + 3) * 128 + r] = va.w;
            float4 vb = *(const float4*)&Bm[(size_t)(j0 + r) * 64 + c0 + q * 4];
            Bs[(q * 4 + 0) * 128 + r] = vb.x;
            Bs[(q * 4 + 1) * 128 + r] = vb.y;
            Bs[(q * 4 + 2) * 128 + r] = vb.z;
            Bs[(q * 4 + 3) * 128 + r] = vb.w;
        }
        __syncthreads();
        #pragma unroll
        for (int k = 0; k < 16; k++) {
            float a[8], bb[8];
            *(float4*)&a[0]  = *(const float4*)&As[k * 128 + ty * 8];
            *(float4*)&a[4]  = *(const float4*)&As[k * 128 + ty * 8 + 4];
            *(float4*)&bb[0] = *(const float4*)&Bs[k * 128 + tx * 8];
            *(float4*)&bb[4] = *(const float4*)&Bs[k * 128 + tx * 8 + 4];
            #pragma unroll
            for (int r = 0; r < 8; r++)
                #pragma unroll
                for (int c = 0; c < 8; c++)
                    acc[r][c] = fmaf(a[r], bb[c], acc[r][c]);
        }
        __syncthreads();
    }

    float sj[8];
    #pragma unroll
    for (int c = 0; c < 8; c++) sj[c] = sqb[j0 + tx * 8 + c];

    #pragma unroll
    for (int r = 0; r < 8; r++) {
        int i = i0 + ty * 8 + r;
        float si = sqa[i];
        float o[8];
        #pragma unroll
        for (int c = 0; c < 8; c++)
            o[c] = 0.5f * (si + sj[c] - 2.f * acc[r][c]);
        float* dst = &C[(size_t)i * NP + j0 + tx * 8];
        *(float4*)&dst[0] = *(float4*)&o[0];
        *(float4*)&dst[4] = *(float4*)&o[4];
    }
}

// ---------------------------------------------------------------------------
// transpose C -> CT (32x32 smem tiles)
// ---------------------------------------------------------------------------
__global__ void transpose_kernel(const float* __restrict__ A, float* __restrict__ B) {
    __shared__ float t[32][33];
    int x = blockIdx.x * 32 + threadIdx.x;
    int y = blockIdx.y * 32 + threadIdx.y;
    #pragma unroll
    for (int j = 0; j < 32; j += 8)
        t[threadIdx.y + j][threadIdx.x] = A[(size_t)(y + j) * NP + x];
    __syncthreads();
    x = blockIdx.y * 32 + threadIdx.x;
    y = blockIdx.x * 32 + threadIdx.y;
    #pragma unroll
    for (int j = 0; j < 32; j += 8)
        B[(size_t)(y + j) * NP + x] = t[threadIdx.x][threadIdx.y + j];
}

// ---------------------------------------------------------------------------
// quantize one row: u = round((C - rmin)/scl), scl = (rmax-rmin)/65535.
// ---------------------------------------------------------------------------
__global__ void __launch_bounds__(256) quant_kernel(
        const float* __restrict__ Cf, unsigned short* __restrict__ Q,
        float* __restrict__ off, float* __restrict__ scl) {
    __shared__ float rmn[256], rmx[256];
    __shared__ float s_min, s_inv;
    int row = blockIdx.x, tid = threadIdx.x;
    const float4* r4 = (const float4*)(Cf + (size_t)row * NP);
    float mn = INFINITY, mx = -INFINITY;
    float4 a[4];
    #pragma unroll
    for (int k = 0; k < 4; k++) {
        float4 v = r4[tid * 4 + k];
        a[k] = v;
        mn = fminf(mn, fminf(fminf(v.x, v.y), fminf(v.z, v.w)));
        mx = fmaxf(mx, fmaxf(fmaxf(v.x, v.y), fmaxf(v.z, v.w)));
    }
    rmn[tid] = mn; rmx[tid] = mx;
    __syncthreads();
    for (int s = 128; s; s >>= 1) {
        if (tid < s) {
            rmn[tid] = fminf(rmn[tid], rmn[tid + s]);
            rmx[tid] = fmaxf(rmx[tid], rmx[tid + s]);
        }
        __syncthreads();
    }
    if (tid == 0) {
        float lo = rmn[0], hi = rmx[0];
        float q = fmaxf((hi - lo) / 65535.0f, 1e-12f);
        off[row] = lo; scl[row] = q;
        s_min = lo; s_inv = 1.0f / q;
    }
    __syncthreads();
    float lo = s_min, qi = s_inv;
    unsigned us[16];
    #pragma unroll
    for (int k = 0; k < 4; k++) {
        us[k*4+0] = (unsigned)fminf(fmaxf(rintf((a[k].x - lo) * qi), 0.f), 65535.f);
        us[k*4+1] = (unsigned)fminf(fmaxf(rintf((a[k].y - lo) * qi), 0.f), 65535.f);
        us[k*4+2] = (unsigned)fminf(fmaxf(rintf((a[k].z - lo) * qi), 0.f), 65535.f);
        us[k*4+3] = (unsigned)fminf(fmaxf(rintf((a[k].w - lo) * qi), 0.f), 65535.f);
    }
    uint4* q4 = (uint4*)(Q + (size_t)row * NP);
    uint4 w0, w1;
    w0.x = us[0]  | (us[1]  << 16); w0.y = us[2]  | (us[3]  << 16);
    w0.z = us[4]  | (us[5]  << 16); w0.w = us[6]  | (us[7]  << 16);
    w1.x = us[8]  | (us[9]  << 16); w1.y = us[10] | (us[11] << 16);
    w1.z = us[12] | (us[13] << 16); w1.w = us[14] | (us[15] << 16);
    q4[tid * 2]     = w0;
    q4[tid * 2 + 1] = w1;
}

// ---------------------------------------------------------------------------
// u16 -> float decode (exact): (0x4B000000 | u) as float == 2^23 + u
// ---------------------------------------------------------------------------
__device__ __forceinline__ float u16lo(unsigned w) {
    return __uint_as_float(__byte_perm(w, 0x4B000000u, 0x7410)) - 8388608.0f;
}
__device__ __forceinline__ float u16hi(unsigned w) {
    return __uint_as_float(__byte_perm(w, 0x4B000000u, 0x7432)) - 8388608.0f;
}

// one 16-element chunk of the online LSE, with safe negligibility skip.
__device__ __forceinline__ void chunk16q(uint4 a0, uint4 a1,
                                         const float4* __restrict__ h,
                                         float kq, float& m, float& s) {
    float4 h0 = h[0], h1 = h[1], h2 = h[64], h3 = h[65];
    float v[16];
    v[0]  = fmaf(u16lo(a0.x), kq, h0.x); v[1]  = fmaf(u16hi(a0.x), kq, h0.y);
    v[2]  = fmaf(u16lo(a0.y), kq, h0.z); v[3]  = fmaf(u16hi(a0.y), kq, h0.w);
    v[4]  = fmaf(u16lo(a0.z), kq, h1.x); v[5]  = fmaf(u16hi(a0.z), kq, h1.y);
    v[6]  = fmaf(u16lo(a0.w), kq, h1.z); v[7]  = fmaf(u16hi(a0.w), kq, h1.w);
    v[8]  = fmaf(u16lo(a1.x), kq, h2.x); v[9]  = fmaf(u16hi(a1.x), kq, h2.y);
    v[10] = fmaf(u16lo(a1.y), kq, h2.z); v[11] = fmaf(u16hi(a1.y), kq, h2.w);
    v[12] = fmaf(u16lo(a1.z), kq, h3.x); v[13] = fmaf(u16hi(a1.z), kq, h3.y);
    v[14] = fmaf(u16lo(a1.w), kq, h3.z); v[15] = fmaf(u16hi(a1.w), kq, h3.w);
    float cm = v[0];
    #pragma unroll
    for (int t = 1; t < 16; t++) cm = fmaxf(cm, v[t]);
    // skipped chunk contributes < 16*2^-25 of exp2(m) <= s; across <=128
    // chunks that's < 6e-5 relative in s -> ~1e-4 log2 units. Negligible.
    if (__all_sync(0xffffffffu, cm < m - 25.0f)) return;
    float cs = 0.f;
    #pragma unroll
    for (int t = 0; t < 16; t++) cs += ex2(v[t] - cm);
    float nm = fmaxf(m, cm);
    s = s * ex2(m - nm) + cs * ex2(cm - nm);
    m = nm;
}

// dual-stream LSE over quantized rows (A default policy, B L2-only).
__device__ __forceinline__ float2 row_lse_dual_q(
        const uint4* __restrict__ QA4, const uint4* __restrict__ QB4,
        const float4* __restrict__ HA, const float4* __restrict__ HB,
        float kqA, float kqB, int lane) {
    float mA = -INFINITY, sA = 0.f;
    float mB = -INFINITY, sB = 0.f;
    #pragma unroll
    for (int seg = 0; seg < 8; seg++) {
        int sa = seg * 64 + lane;
        uint4 a0 = QA4[sa], a1 = QA4[sa + 32];
        uint4 b0 = __ldcg(QB4 + sa), b1 = __ldcg(QB4 + sa + 32);
        chunk16q(a0, a1, HA + sa * 2, kqA, mA, sA);
        chunk16q(b0, b1, HB + sa * 2, kqB, mB, sB);
    }
    #pragma unroll
    for (int off = 16; off; off >>= 1) {
        float om = __shfl_xor_sync(0xffffffffu, mA, off);
        float os = __shfl_xor_sync(0xffffffffu, sA, off);
        float nm = fmaxf(mA, om);
        sA = sA * ex2(mA - nm) + os * ex2(om - nm);
        mA = nm;
        float om2 = __shfl_xor_sync(0xffffffffu, mB, off);
        float os2 = __shfl_xor_sync(0xffffffffu, sB, off);
        float nm2 = fmaxf(mB, om2);
        sB = sB * ex2(mB - nm2) + os2 * ex2(om2 - nm2);
        mB = nm2;
    }
    return make_float2(mA + lg2(sA), mB + lg2(sB));
}

__device__ __forceinline__ void init_eps(float* sh_eps, int tid) {
    if (tid < 56) {
        double e = (tid < 55)
            ? exp(5.545177444479562 - 0.21072103131565253 * (double)tid)
            : 0.0025;
        sh_eps[tid] = (float)e;
    }
}

__device__ __forceinline__ void fill_bias(float* sh, const float* pot,
                                          float inv_e, int tid) {
    const float4* p4 = (const float4*)pot;
    float4* s4 = (float4*)sh;
    #pragma unroll
    for (int q = 0; q < 2; q++) {
        int j = tid + q * 512;
        float4 v = __ldcg(p4 + j);
        float4 o;
        o.x = fmaf(v.x, inv_e, NEG_LOGN) * LOG2E;
        o.y = fmaf(v.y, inv_e, NEG_LOGN) * LOG2E;
        o.z = fmaf(v.z, inv_e, NEG_LOGN) * LOG2E;
        o.w = fmaf(v.w, inv_e, NEG_LOGN) * LOG2E;
        s4[j] = o;
    }
}

// ---------------------------------------------------------------------------
// dual annealing phase on quantized matrices.
// true val = off[row] - eps*ln2*lse_u   (row offset re-added exactly)
// ---------------------------------------------------------------------------
__global__ void __launch_bounds__(512, 2) dual_phase_kernel(
        const unsigned short* __restrict__ QA, const unsigned short* __restrict__ QB,
        const float* __restrict__ offA, const float* __restrict__ sclA,
        const float* __restrict__ offB, const float* __restrict__ sclB,
        float* __restrict__ bA0, float* __restrict__ bA1,
        float* __restrict__ uA0, float* __restrict__ uA1,
        float* __restrict__ bB0, float* __restrict__ bB1,
        float* __restrict__ uB0, float* __restrict__ uB1,
        float* __restrict__ outA, float* __restrict__ outB) {
    __shared__ __align__(16) float shA[NP];
    __shared__ __align__(16) float shB[NP];
    __shared__ float sh_eps[56];
    int tid = threadIdx.x, lane = tid & 31, warp = tid >> 5;
    int row = warp * NBLK + (int)blockIdx.x;
    bool active = row < NP;
    int prow = active ? row : 0;
    init_eps(sh_eps, tid);
    const uint4* QA4 = (const uint4*)(QA + (size_t)prow * NP);
    const uint4* QB4 = (const uint4*)(QB + (size_t)prow * NP);
    float oA = offA[prow], qA = sclA[prow];
    float oB = offB[prow], qB = sclB[prow];
    float* bA[2] = { bA0, bA1 };
    float* uA[2] = { uA0, uA1 };
    float* bB[2] = { bB0, bB1 };
    float* uB[2] = { uB0, uB1 };
    int cur = 0;
    __syncthreads();

    for (int t = 0; t <= 57; t++) {
        int ke = (t == 0) ? 0 : (t == 57 ? 55 : t - 1);
        float e = sh_eps[ke];
        float inv_e = 1.f / e;
        float kqA = -qA * inv_e * LOG2E;
        float kqB = -qB * inv_e * LOG2E;

        if (t == 0) {
            for (int j = tid; j < NP; j += 512) {
                shA[j] = NEG_LOGN * LOG2E;
                shB[j] = NEG_LOGN * LOG2E;
            }
        } else {
            fill_bias(shA, bA[cur], inv_e, tid);
            fill_bias(shB, bB[cur], inv_e, tid);
        }
        __syncthreads();

        float2 ls = row_lse_dual_q(QA4, QB4, (const float4*)shA,
                                   (const float4*)shB, kqA, kqB, lane);

        if (lane == 0 && active) {
            float vA = oA - e * LN2 * ls.x;
            float vB = oB - e * LN2 * ls.y;
            if (t == 57) {
                outA[row] = vA;
                outB[row] = vB;
            } else if (t == 0) {
                __stcg(&uA[1][row], vA);
                __stcg(&uB[1][row], vB);
            } else {
                __stcg(&uA[cur ^ 1][row],
                       0.5f * __ldcg(&uA[cur][row]) + 0.5f * vA);
                __stcg(&uB[cur ^ 1][row],
                       0.5f * __ldcg(&uB[cur][row]) + 0.5f * vB);
            }
        }
        if (t == 0) cur = 1; else if (t < 57) cur ^= 1;
        if (t < 57) gsync();
    }
}

// ---------------------------------------------------------------------------
__global__ void loss_reduce(const float* __restrict__ fin, float* __restrict__ out, int first) {
    __shared__ float red[256];
    int tid = threadIdx.x;
    float a = 0.f;
    for (int j = tid; j < NP; j += 256)
        a += (fin[2 * NP + j] - fin[0 * NP + j]) + (fin[3 * NP + j] - fin[1 * NP + j]);
    red[tid] = a;
    __syncthreads();
    for (int sft = 128; sft; sft >>= 1) {
        if (tid < sft) red[tid] += red[tid + sft];
        __syncthreads();
    }
    if (tid == 0) {
        float v = red[0] * (1.0f / NP) * 0.25f;
        if (first) *out = v; else *out += v;
    }
}

// ---------------------------------------------------------------------------
extern "C" void kernel_launch(void* const* d_in, const int* in_sizes, int n_in,
                              void* d_out, int out_size) {
    (void)in_sizes; (void)n_in; (void)out_size;
    const float* x = (const float*)d_in[0];
    const float* y = (const float*)d_in[1];
    float* out = (float*)d_out;

    Scratch* sp = nullptr;
    cudaGetSymbolAddress((void**)&sp, S);
    float* Cf  = sp->Cf;  float* CTf = sp->CTf;
    float* xt  = sp->xt;  float* yt  = sp->yt;
    float* sqx = sp->sqx; float* sqy = sp->sqy;
    float* f0 = sp->f[0]; float* f1 = sp->f[1];
    float* g0 = sp->g[0]; float* g1 = sp->g[1];
    float* fin = (float*)sp->fin;

    for (int b = 0; b < 4; b++) {
        const float* xb = x + (size_t)b * 64 * NP;
        const float* yb = y + (size_t)b * 64 * NP;

        // launch #6 of batch 0 = dual_phase_kernel (ncu -s 5 -c 1 target)
        prep_kernel<<<16, 256>>>(xb, yb, xt, yt, sqx, sqy);            // 1
        cost_kernel<<<dim3(32, 32), 256>>>(xt, xt, sqx, sqx, Cf);      // 2
        quant_kernel<<<NP, 256>>>(Cf, sp->Qxx, sp->oxx, sp->sxx);      // 3
        cost_kernel<<<dim3(32, 32), 256>>>(yt, yt, sqy, sqy, Cf);      // 4
        quant_kernel<<<NP, 256>>>(Cf, sp->Qyy, sp->oyy, sp->syy);      // 5

        // fused xx+yy phase (self-coupled streams)                    // 6
        dual_phase_kernel<<<NBLK, 512>>>(sp->Qxx, sp->Qyy,
                                         sp->oxx, sp->sxx, sp->oyy, sp->syy,
                                         f0, f1, f0, f1,
                                         g0, g1, g0, g1,
                                         fin + 0 * NP, fin + 1 * NP);

        cost_kernel<<<dim3(32, 32), 256>>>(xt, yt, sqx, sqy, Cf);
        transpose_kernel<<<dim3(128, 128), dim3(32, 8)>>>(Cf, CTf);
        quant_kernel<<<NP, 256>>>(Cf,  sp->QD,  sp->oD,  sp->sD);
        quant_kernel<<<NP, 256>>>(CTf, sp->QDT, sp->oDT, sp->sDT);

        // xy phase (cross-coupled)
        dual_phase_kernel<<<NBLK, 512>>>(sp->QD, sp->QDT,
                                         sp->oD, sp->sD, sp->oDT, sp->sDT,
                                         g0, g1, f0, f1,
                                         f0, f1, g0, g1,
                                         fin + 2 * NP, fin + 3 * NP);

        loss_reduce<<<1, 256>>>(fin, out, b == 0 ? 1 : 0);
    }
}

// round 12
// speedup vs baseline: 1.1180x; 1.0012x over previous
#include <cuda_runtime.h>
#include <math.h>

#define NP 4096
#define NBLK 296
#define NEG_LOGN (-8.317766166719343f)   /* -log(4096) */
#define LOG2E 1.4426950408889634f
#define LN2   0.6931471805599453f

struct __align__(16) Scratch {
    float Cf [(size_t)NP * NP];            // 64 MB fp32 staging
    float CTf[(size_t)NP * NP];            // 64 MB fp32 staging (transpose)
    unsigned short Qxx[(size_t)NP * NP];   // 32 MB quantized
    unsigned short Qyy[(size_t)NP * NP];
    unsigned short QD [(size_t)NP * NP];
    unsigned short QDT[(size_t)NP * NP];
    float oxx[NP], sxx[NP];                // per-row offset + scale
    float oyy[NP], syy[NP];
    float oD [NP], sD [NP];
    float oDT[NP], sDT[NP];
    float xt[NP * 64], yt[NP * 64];
    float sqx[NP], sqy[NP];
    float f[2][NP], g[2][NP];
    float fin[4][NP];
};
__device__ Scratch S;

// single-instruction MUFU ops
__device__ __forceinline__ float ex2(float x) {
    float y;
    asm("ex2.approx.ftz.f32 %0, %1;" : "=f"(y) : "f"(x));
    return y;
}
__device__ __forceinline__ float lg2(float x) {
    float y;
    asm("lg2.approx.f32 %0, %1;" : "=f"(y) : "f"(x));
    return y;
}

// ---------------------------------------------------------------------------
// software grid barrier (NBLK blocks, 2/SM co-resident via launch_bounds)
// hot spin: spinner is 1 thread of 512, its issue cost is negligible, and
// wake latency matters (456 barriers per run).
// ---------------------------------------------------------------------------
__device__ unsigned g_cnt;
__device__ unsigned g_gen;

__device__ __forceinline__ void gsync() {
    __threadfence();
    __syncthreads();
    if (threadIdx.x == 0) {
        volatile unsigned* vg = &g_gen;
        unsigned my = *vg;
        if (atomicAdd(&g_cnt, 1u) == NBLK - 1u) {
            g_cnt = 0u;
            __threadfence();
            *vg = my + 1u;
        } else {
            while (*vg == my) { }
        }
    }
    __syncthreads();
}

// ---------------------------------------------------------------------------
__global__ void prep_kernel(const float* __restrict__ x, const float* __restrict__ y,
                            float* __restrict__ xt, float* __restrict__ yt,
                            float* __restrict__ sqx, float* __restrict__ sqy) {
    int p = blockIdx.x * blockDim.x + threadIdx.x;
    float sx = 0.f, sy = 0.f;
    #pragma unroll 8
    for (int c = 0; c < 64; c++) {
        float vx = x[c * NP + p];
        float vy = y[c * NP + p];
        xt[p * 64 + c] = vx;
        yt[p * 64 + c] = vy;
        sx = fmaf(vx, vx, sx);
        sy = fmaf(vy, vy, sy);
    }
    sqx[p] = sx; sqy[p] = sy;
}

// ---------------------------------------------------------------------------
// cost: C[i][j] = 0.5*(|a_i|^2 + |b_j|^2 - 2 a_i.b_j)
// ---------------------------------------------------------------------------
__global__ void cost_kernel(const float* __restrict__ A, const float* __restrict__ Bm,
                            const float* __restrict__ sqa, const float* __restrict__ sqb,
                            float* __restrict__ C) {
    __shared__ float As[16 * 128];
    __shared__ float Bs[16 * 128];
    int tid = threadIdx.x;
    int tx = tid & 15, ty = tid >> 4;
    int i0 = blockIdx.y * 128, j0 = blockIdx.x * 128;

    float acc[8][8];
    #pragma unroll
    for (int r = 0; r < 8; r++)
        #pragma unroll
        for (int c = 0; c < 8; c++) acc[r][c] = 0.f;

    for (int c0 = 0; c0 < 64; c0 += 16) {
        #pragma unroll
        for (int n = 0; n < 2; n++) {
            int idx = tid + n * 256;
            int r = idx >> 2, q = idx & 3;
            float4 va = *(const float4*)&A[(size_t)(i0 + r) * 64 + c0 + q * 4];
            As[(q * 4 + 0) * 128 + r] = va.x;
            As[(q * 4 + 1) * 128 + r] = va.y;
            As[(q * 4 + 2) * 128 + r] = va.z;
            As[(q * 4 + 3) * 128 + r] = va.w;
            float4 vb = *(const float4*)&Bm[(size_t)(j0 + r) * 64 + c0 + q * 4];
            Bs[(q * 4 + 0) * 128 + r] = vb.x;
            Bs[(q * 4 + 1) * 128 + r] = vb.y;
            Bs[(q * 4 + 2) * 128 + r] = vb.z;
            Bs[(q * 4 + 3) * 128 + r] = vb.w;
        }
        __syncthreads();
        #pragma unroll
        for (int k = 0; k < 16; k++) {
            float a[8], bb[8];
            *(float4*)&a[0]  = *(const float4*)&As[k * 128 + ty * 8];
            *(float4*)&a[4]  = *(const float4*)&As[k * 128 + ty * 8 + 4];
            *(float4*)&bb[0] = *(const float4*)&Bs[k * 128 + tx * 8];
            *(float4*)&bb[4] = *(const float4*)&Bs[k * 128 + tx * 8 + 4];
            #pragma unroll
            for (int r = 0; r < 8; r++)
                #pragma unroll
                for (int c = 0; c < 8; c++)
                    acc[r][c] = fmaf(a[r], bb[c], acc[r][c]);
        }
        __syncthreads();
    }

    float sj[8];
    #pragma unroll
    for (int c = 0; c < 8; c++) sj[c] = sqb[j0 + tx * 8 + c];

    #pragma unroll
    for (int r = 0; r < 8; r++) {
        int i = i0 + ty * 8 + r;
        float si = sqa[i];
        float o[8];
        #pragma unroll
        for (int c = 0; c < 8; c++)
            o[c] = 0.5f * (si + sj[c] - 2.f * acc[r][c]);
        float* dst = &C[(size_t)i * NP + j0 + tx * 8];
        *(float4*)&dst[0] = *(float4*)&o[0];
        *(float4*)&dst[4] = *(float4*)&o[4];
    }
}

// ---------------------------------------------------------------------------
// transpose C -> CT (32x32 smem tiles)
// ---------------------------------------------------------------------------
__global__ void transpose_kernel(const float* __restrict__ A, float* __restrict__ B) {
    __shared__ float t[32][33];
    int x = blockIdx.x * 32 + threadIdx.x;
    int y = blockIdx.y * 32 + threadIdx.y;
    #pragma unroll
    for (int j = 0; j < 32; j += 8)
        t[threadIdx.y + j][threadIdx.x] = A[(size_t)(y + j) * NP + x];
    __syncthreads();
    x = blockIdx.y * 32 + threadIdx.x;
    y = blockIdx.x * 32 + threadIdx.y;
    #pragma unroll
    for (int j = 0; j < 32; j += 8)
        B[(size_t)(y + j) * NP + x] = t[threadIdx.x][threadIdx.y + j];
}

// ---------------------------------------------------------------------------
// quantize one row: u = round((C - rmin)/scl), scl = (rmax-rmin)/65535.
// ---------------------------------------------------------------------------
__global__ void __launch_bounds__(256) quant_kernel(
        const float* __restrict__ Cf, unsigned short* __restrict__ Q,
        float* __restrict__ off, float* __restrict__ scl) {
    __shared__ float rmn[256], rmx[256];
    __shared__ float s_min, s_inv;
    int row = blockIdx.x, tid = threadIdx.x;
    const float4* r4 = (const float4*)(Cf + (size_t)row * NP);
    float mn = INFINITY, mx = -INFINITY;
    float4 a[4];
    #pragma unroll
    for (int k = 0; k < 4; k++) {
        float4 v = r4[tid * 4 + k];
        a[k] = v;
        mn = fminf(mn, fminf(fminf(v.x, v.y), fminf(v.z, v.w)));
        mx = fmaxf(mx, fmaxf(fmaxf(v.x, v.y), fmaxf(v.z, v.w)));
    }
    rmn[tid] = mn; rmx[tid] = mx;
    __syncthreads();
    for (int s = 128; s; s >>= 1) {
        if (tid < s) {
            rmn[tid] = fminf(rmn[tid], rmn[tid + s]);
            rmx[tid] = fmaxf(rmx[tid], rmx[tid + s]);
        }
        __syncthreads();
    }
    if (tid == 0) {
        float lo = rmn[0], hi = rmx[0];
        float q = fmaxf((hi - lo) / 65535.0f, 1e-12f);
        off[row] = lo; scl[row] = q;
        s_min = lo; s_inv = 1.0f / q;
    }
    __syncthreads();
    float lo = s_min, qi = s_inv;
    unsigned us[16];
    #pragma unroll
    for (int k = 0; k < 4; k++) {
        us[k*4+0] = (unsigned)fminf(fmaxf(rintf((a[k].x - lo) * qi), 0.f), 65535.f);
        us[k*4+1] = (unsigned)fminf(fmaxf(rintf((a[k].y - lo) * qi), 0.f), 65535.f);
        us[k*4+2] = (unsigned)fminf(fmaxf(rintf((a[k].z - lo) * qi), 0.f), 65535.f);
        us[k*4+3] = (unsigned)fminf(fmaxf(rintf((a[k].w - lo) * qi), 0.f), 65535.f);
    }
    uint4* q4 = (uint4*)(Q + (size_t)row * NP);
    uint4 w0, w1;
    w0.x = us[0]  | (us[1]  << 16); w0.y = us[2]  | (us[3]  << 16);
    w0.z = us[4]  | (us[5]  << 16); w0.w = us[6]  | (us[7]  << 16);
    w1.x = us[8]  | (us[9]  << 16); w1.y = us[10] | (us[11] << 16);
    w1.z = us[12] | (us[13] << 16); w1.w = us[14] | (us[15] << 16);
    q4[tid * 2]     = w0;
    q4[tid * 2 + 1] = w1;
}

// ---------------------------------------------------------------------------
// u16 -> float decode (exact): (0x4B000000 | u) as float == 2^23 + u
// ---------------------------------------------------------------------------
__device__ __forceinline__ float u16lo(unsigned w) {
    return __uint_as_float(__byte_perm(w, 0x4B000000u, 0x7410)) - 8388608.0f;
}
__device__ __forceinline__ float u16hi(unsigned w) {
    return __uint_as_float(__byte_perm(w, 0x4B000000u, 0x7432)) - 8388608.0f;
}

// one 16-element chunk of the online LSE, with safe negligibility skip.
__device__ __forceinline__ void chunk16q(uint4 a0, uint4 a1,
                                         const float4* __restrict__ h,
                                         float kq, float& m, float& s) {
    float4 h0 = h[0], h1 = h[1], h2 = h[64], h3 = h[65];
    float v[16];
    v[0]  = fmaf(u16lo(a0.x), kq, h0.x); v[1]  = fmaf(u16hi(a0.x), kq, h0.y);
    v[2]  = fmaf(u16lo(a0.y), kq, h0.z); v[3]  = fmaf(u16hi(a0.y), kq, h0.w);
    v[4]  = fmaf(u16lo(a0.z), kq, h1.x); v[5]  = fmaf(u16hi(a0.z), kq, h1.y);
    v[6]  = fmaf(u16lo(a0.w), kq, h1.z); v[7]  = fmaf(u16hi(a0.w), kq, h1.w);
    v[8]  = fmaf(u16lo(a1.x), kq, h2.x); v[9]  = fmaf(u16hi(a1.x), kq, h2.y);
    v[10] = fmaf(u16lo(a1.y), kq, h2.z); v[11] = fmaf(u16hi(a1.y), kq, h2.w);
    v[12] = fmaf(u16lo(a1.z), kq, h3.x); v[13] = fmaf(u16hi(a1.z), kq, h3.y);
    v[14] = fmaf(u16lo(a1.w), kq, h3.z); v[15] = fmaf(u16hi(a1.w), kq, h3.w);
    float cm = v[0];
    #pragma unroll
    for (int t = 1; t < 16; t++) cm = fmaxf(cm, v[t]);
    // skipped chunk contributes < 16*2^-25 of exp2(m) <= s; across <=128
    // chunks that's < 6e-5 relative in s. Negligible.
    if (__all_sync(0xffffffffu, cm < m - 25.0f)) return;
    float cs = 0.f;
    #pragma unroll
    for (int t = 0; t < 16; t++) cs += ex2(v[t] - cm);
    float nm = fmaxf(m, cm);
    s = s * ex2(m - nm) + cs * ex2(cm - nm);
    m = nm;
}

// dual-stream LSE, software-pipelined: next segment's 4 LDG.128 issue before
// current segment's chunks are processed -> L2 latency covered by compute.
__device__ __forceinline__ float2 row_lse_dual_q(
        const uint4* __restrict__ QA4, const uint4* __restrict__ QB4,
        const float4* __restrict__ HA, const float4* __restrict__ HB,
        float kqA, float kqB, int lane) {
    float mA = -INFINITY, sA = 0.f;
    float mB = -INFINITY, sB = 0.f;
    uint4 a0 = QA4[lane],          a1 = QA4[lane + 32];
    uint4 b0 = __ldcg(QB4 + lane), b1 = __ldcg(QB4 + lane + 32);
    #pragma unroll
    for (int seg = 0; seg < 8; seg++) {
        uint4 na0, na1, nb0, nb1;
        if (seg < 7) {
            int sn = (seg + 1) * 64 + lane;
            na0 = QA4[sn];          na1 = QA4[sn + 32];
            nb0 = __ldcg(QB4 + sn); nb1 = __ldcg(QB4 + sn + 32);
        }
        int sa = seg * 64 + lane;
        chunk16q(a0, a1, HA + sa * 2, kqA, mA, sA);
        chunk16q(b0, b1, HB + sa * 2, kqB, mB, sB);
        a0 = na0; a1 = na1; b0 = nb0; b1 = nb1;
    }
    #pragma unroll
    for (int off = 16; off; off >>= 1) {
        float om = __shfl_xor_sync(0xffffffffu, mA, off);
        float os = __shfl_xor_sync(0xffffffffu, sA, off);
        float nm = fmaxf(mA, om);
        sA = sA * ex2(mA - nm) + os * ex2(om - nm);
        mA = nm;
        float om2 = __shfl_xor_sync(0xffffffffu, mB, off);
        float os2 = __shfl_xor_sync(0xffffffffu, sB, off);
        float nm2 = fmaxf(mB, om2);
        sB = sB * ex2(mB - nm2) + os2 * ex2(om2 - nm2);
        mB = nm2;
    }
    return make_float2(mA + lg2(sA), mB + lg2(sB));
}

__device__ __forceinline__ void init_eps(float* sh_eps, int tid) {
    if (tid < 56) {
        double e = (tid < 55)
            ? exp(5.545177444479562 - 0.21072103131565253 * (double)tid)
            : 0.0025;
        sh_eps[tid] = (float)e;
    }
}

__device__ __forceinline__ void fill_bias(float* sh, const float* pot,
                                          float inv_e, int tid) {
    const float4* p4 = (const float4*)pot;
    float4* s4 = (float4*)sh;
    #pragma unroll
    for (int q = 0; q < 2; q++) {
        int j = tid + q * 512;
        float4 v = __ldcg(p4 + j);
        float4 o;
        o.x = fmaf(v.x, inv_e, NEG_LOGN) * LOG2E;
        o.y = fmaf(v.y, inv_e, NEG_LOGN) * LOG2E;
        o.z = fmaf(v.z, inv_e, NEG_LOGN) * LOG2E;
        o.w = fmaf(v.w, inv_e, NEG_LOGN) * LOG2E;
        s4[j] = o;
    }
}

// ---------------------------------------------------------------------------
// dual annealing phase on quantized matrices.
// true val = off[row] - eps*ln2*lse_u   (row offset re-added exactly)
// ---------------------------------------------------------------------------
__global__ void __launch_bounds__(512, 2) dual_phase_kernel(
        const unsigned short* __restrict__ QA, const unsigned short* __restrict__ QB,
        const float* __restrict__ offA, const float* __restrict__ sclA,
        const float* __restrict__ offB, const float* __restrict__ sclB,
        float* __restrict__ bA0, float* __restrict__ bA1,
        float* __restrict__ uA0, float* __restrict__ uA1,
        float* __restrict__ bB0, float* __restrict__ bB1,
        float* __restrict__ uB0, float* __restrict__ uB1,
        float* __restrict__ outA, float* __restrict__ outB) {
    __shared__ __align__(16) float shA[NP];
    __shared__ __align__(16) float shB[NP];
    __shared__ float sh_eps[56];
    int tid = threadIdx.x, lane = tid & 31, warp = tid >> 5;
    int row = warp * NBLK + (int)blockIdx.x;
    bool active = row < NP;
    int prow = active ? row : 0;
    init_eps(sh_eps, tid);
    const uint4* QA4 = (const uint4*)(QA + (size_t)prow * NP);
    const uint4* QB4 = (const uint4*)(QB + (size_t)prow * NP);
    float oA = offA[prow], qA = sclA[prow];
    float oB = offB[prow], qB = sclB[prow];
    float* bA[2] = { bA0, bA1 };
    float* uA[2] = { uA0, uA1 };
    float* bB[2] = { bB0, bB1 };
    float* uB[2] = { uB0, uB1 };
    int cur = 0;
    __syncthreads();

    for (int t = 0; t <= 57; t++) {
        int ke = (t == 0) ? 0 : (t == 57 ? 55 : t - 1);
        float e = sh_eps[ke];
        float inv_e = 1.f / e;
        float kqA = -qA * inv_e * LOG2E;
        float kqB = -qB * inv_e * LOG2E;

        if (t == 0) {
            for (int j = tid; j < NP; j += 512) {
                shA[j] = NEG_LOGN * LOG2E;
                shB[j] = NEG_LOGN * LOG2E;
            }
        } else {
            fill_bias(shA, bA[cur], inv_e, tid);
            fill_bias(shB, bB[cur], inv_e, tid);
        }
        __syncthreads();

        float2 ls = row_lse_dual_q(QA4, QB4, (const float4*)shA,
                                   (const float4*)shB, kqA, kqB, lane);

        if (lane == 0 && active) {
            float vA = oA - e * LN2 * ls.x;
            float vB = oB - e * LN2 * ls.y;
            if (t == 57) {
                outA[row] = vA;
                outB[row] = vB;
            } else if (t == 0) {
                __stcg(&uA[1][row], vA);
                __stcg(&uB[1][row], vB);
            } else {
                __stcg(&uA[cur ^ 1][row],
                       0.5f * __ldcg(&uA[cur][row]) + 0.5f * vA);
                __stcg(&uB[cur ^ 1][row],
                       0.5f * __ldcg(&uB[cur][row]) + 0.5f * vB);
            }
        }
        if (t == 0) cur = 1; else if (t < 57) cur ^= 1;
        if (t < 57) gsync();
    }
}

// ---------------------------------------------------------------------------
__global__ void loss_reduce(const float* __restrict__ fin, float* __restrict__ out, int first) {
    __shared__ float red[256];
    int tid = threadIdx.x;
    float a = 0.f;
    for (int j = tid; j < NP; j += 256)
        a += (fin[2 * NP + j] - fin[0 * NP + j]) + (fin[3 * NP + j] - fin[1 * NP + j]);
    red[tid] = a;
    __syncthreads();
    for (int sft = 128; sft; sft >>= 1) {
        if (tid < sft) red[tid] += red[tid + sft];
        __syncthreads();
    }
    if (tid == 0) {
        float v = red[0] * (1.0f / NP) * 0.25f;
        if (first) *out = v; else *out += v;
    }
}

// ---------------------------------------------------------------------------
extern "C" void kernel_launch(void* const* d_in, const int* in_sizes, int n_in,
                              void* d_out, int out_size) {
    (void)in_sizes; (void)n_in; (void)out_size;
    const float* x = (const float*)d_in[0];
    const float* y = (const float*)d_in[1];
    float* out = (float*)d_out;

    Scratch* sp = nullptr;
    cudaGetSymbolAddress((void**)&sp, S);
    float* Cf  = sp->Cf;  float* CTf = sp->CTf;
    float* xt  = sp->xt;  float* yt  = sp->yt;
    float* sqx = sp->sqx; float* sqy = sp->sqy;
    float* f0 = sp->f[0]; float* f1 = sp->f[1];
    float* g0 = sp->g[0]; float* g1 = sp->g[1];
    float* fin = (float*)sp->fin;

    for (int b = 0; b < 4; b++) {
        const float* xb = x + (size_t)b * 64 * NP;
        const float* yb = y + (size_t)b * 64 * NP;

        prep_kernel<<<16, 256>>>(xb, yb, xt, yt, sqx, sqy);
        cost_kernel<<<dim3(32, 32), 256>>>(xt, xt, sqx, sqx, Cf);
        quant_kernel<<<NP, 256>>>(Cf, sp->Qxx, sp->oxx, sp->sxx);
        cost_kernel<<<dim3(32, 32), 256>>>(yt, yt, sqy, sqy, Cf);
        quant_kernel<<<NP, 256>>>(Cf, sp->Qyy, sp->oyy, sp->syy);

        // fused xx+yy phase (self-coupled streams)
        dual_phase_kernel<<<NBLK, 512>>>(sp->Qxx, sp->Qyy,
                                         sp->oxx, sp->sxx, sp->oyy, sp->syy,
                                         f0, f1, f0, f1,
                                         g0, g1, g0, g1,
                                         fin + 0 * NP, fin + 1 * NP);

        cost_kernel<<<dim3(32, 32), 256>>>(xt, yt, sqx, sqy, Cf);
        transpose_kernel<<<dim3(128, 128), dim3(32, 8)>>>(Cf, CTf);
        quant_kernel<<<NP, 256>>>(Cf,  sp->QD,  sp->oD,  sp->sD);
        quant_kernel<<<NP, 256>>>(CTf, sp->QDT, sp->oDT, sp->sDT);

        // xy phase (cross-coupled)
        dual_phase_kernel<<<NBLK, 512>>>(sp->QD, sp->QDT,
                                         sp->oD, sp->sD, sp->oDT, sp->sDT,
                                         g0, g1, f0, f1,
                                         f0, f1, g0, g1,
                                         fin + 2 * NP, fin + 3 * NP);

        loss_reduce<<<1, 256>>>(fin, out, b == 0 ? 1 : 0);
    }
}

// round 13
// speedup vs baseline: 1.1527x; 1.0310x over previous
#include <cuda_runtime.h>
#include <math.h>

#define NP 4096
#define NBLK 296
#define NEG_LOGN (-8.317766166719343f)   /* -log(4096) */
#define LOG2E 1.4426950408889634f
#define LN2   0.6931471805599453f

struct __align__(16) Scratch {
    unsigned short Qxx[(size_t)NP * NP];   // 32 MB quantized
    unsigned short Qyy[(size_t)NP * NP];
    unsigned short QD [(size_t)NP * NP];
    unsigned short QDT[(size_t)NP * NP];
    float xt[NP * 64], yt[NP * 64];
    float sqx[NP], sqy[NP];
    float f[2][NP], g[2][NP];
    float fin[4][NP];
};
__device__ Scratch S;

__device__ unsigned g_maxsq;   // max squared norm of the batch (float bits)

// single-instruction MUFU ops
__device__ __forceinline__ float ex2(float x) {
    float y;
    asm("ex2.approx.ftz.f32 %0, %1;" : "=f"(y) : "f"(x));
    return y;
}
__device__ __forceinline__ float lg2(float x) {
    float y;
    asm("lg2.approx.f32 %0, %1;" : "=f"(y) : "f"(x));
    return y;
}

// quantization scale from the batch max norm: C = 0.5|x-y|^2 <= 2*maxsq
__device__ __forceinline__ float q_scale() {
    float ms = fmaxf(__uint_as_float(g_maxsq), 1e-6f);
    return 2.0f * ms * (1.0f / 65535.0f);
}

// ---------------------------------------------------------------------------
// software grid barrier (NBLK blocks, 2/SM co-resident via launch_bounds)
// ---------------------------------------------------------------------------
__device__ unsigned g_cnt;
__device__ unsigned g_gen;

__device__ __forceinline__ void gsync() {
    __threadfence();
    __syncthreads();
    if (threadIdx.x == 0) {
        volatile unsigned* vg = &g_gen;
        unsigned my = *vg;
        if (atomicAdd(&g_cnt, 1u) == NBLK - 1u) {
            g_cnt = 0u;
            __threadfence();
            *vg = my + 1u;
        } else {
            while (*vg == my) { }
        }
    }
    __syncthreads();
}

// ---------------------------------------------------------------------------
__global__ void reset_max_kernel() { g_maxsq = 0u; }

// prep: transpose inputs to point-major, squared norms, batch max norm
__global__ void prep_kernel(const float* __restrict__ x, const float* __restrict__ y,
                            float* __restrict__ xt, float* __restrict__ yt,
                            float* __restrict__ sqx, float* __restrict__ sqy) {
    __shared__ float red[8];
    int p = blockIdx.x * blockDim.x + threadIdx.x;
    float sx = 0.f, sy = 0.f;
    #pragma unroll 8
    for (int c = 0; c < 64; c++) {
        float vx = x[c * NP + p];
        float vy = y[c * NP + p];
        xt[p * 64 + c] = vx;
        yt[p * 64 + c] = vy;
        sx = fmaf(vx, vx, sx);
        sy = fmaf(vy, vy, sy);
    }
    sqx[p] = sx; sqy[p] = sy;
    float mx = fmaxf(sx, sy);
    #pragma unroll
    for (int o = 16; o; o >>= 1)
        mx = fmaxf(mx, __shfl_xor_sync(0xffffffffu, mx, o));
    if ((threadIdx.x & 31) == 0) red[threadIdx.x >> 5] = mx;
    __syncthreads();
    if (threadIdx.x == 0) {
        float m = red[0];
        #pragma unroll
        for (int w = 1; w < 8; w++) m = fmaxf(m, red[w]);
        atomicMax(&g_maxsq, __float_as_uint(m));   // nonneg floats: bit-monotone
    }
}

// ---------------------------------------------------------------------------
// cost + quantize: Q[i][j] = round(0.5*|a_i - b_j|^2 / q), u16, offset 0
// ---------------------------------------------------------------------------
__global__ void cost_quant_kernel(const float* __restrict__ A, const float* __restrict__ Bm,
                                  const float* __restrict__ sqa, const float* __restrict__ sqb,
                                  unsigned short* __restrict__ Q) {
    __shared__ float As[16 * 128];
    __shared__ float Bs[16 * 128];
    int tid = threadIdx.x;
    int tx = tid & 15, ty = tid >> 4;
    int i0 = blockIdx.y * 128, j0 = blockIdx.x * 128;
    float qinv = 1.0f / q_scale();

    float acc[8][8];
    #pragma unroll
    for (int r = 0; r < 8; r++)
        #pragma unroll
        for (int c = 0; c < 8; c++) acc[r][c] = 0.f;

    for (int c0 = 0; c0 < 64; c0 += 16) {
        #pragma unroll
        for (int n = 0; n < 2; n++) {
            int idx = tid + n * 256;
            int r = idx >> 2, q = idx & 3;
            float4 va = *(const float4*)&A[(size_t)(i0 + r) * 64 + c0 + q * 4];
            As[(q * 4 + 0) * 128 + r] = va.x;
            As[(q * 4 + 1) * 128 + r] = va.y;
            As[(q * 4 + 2) * 128 + r] = va.z;
            As[(q * 4 + 3) * 128 + r] = va.w;
            float4 vb = *(const float4*)&Bm[(size_t)(j0 + r) * 64 + c0 + q * 4];
            Bs[(q * 4 + 0) * 128 + r] = vb.x;
            Bs[(q * 4 + 1) * 128 + r] = vb.y;
            Bs[(q * 4 + 2) * 128 + r] = vb.z;
            Bs[(q * 4 + 3) * 128 + r] = vb.w;
        }
        __syncthreads();
        #pragma unroll
        for (int k = 0; k < 16; k++) {
            float a[8], bb[8];
            *(float4*)&a[0]  = *(const float4*)&As[k * 128 + ty * 8];
            *(float4*)&a[4]  = *(const float4*)&As[k * 128 + ty * 8 + 4];
            *(float4*)&bb[0] = *(const float4*)&Bs[k * 128 + tx * 8];
            *(float4*)&bb[4] = *(const float4*)&Bs[k * 128 + tx * 8 + 4];
            #pragma unroll
            for (int r = 0; r < 8; r++)
                #pragma unroll
                for (int c = 0; c < 8; c++)
                    acc[r][c] = fmaf(a[r], bb[c], acc[r][c]);
        }
        __syncthreads();
    }

    float sj[8];
    #pragma unroll
    for (int c = 0; c < 8; c++) sj[c] = sqb[j0 + tx * 8 + c];

    #pragma unroll
    for (int r = 0; r < 8; r++) {
        int i = i0 + ty * 8 + r;
        float si = sqa[i];
        unsigned us[8];
        #pragma unroll
        for (int c = 0; c < 8; c++) {
            float o = 0.5f * (si + sj[c] - 2.f * acc[r][c]);
            us[c] = (unsigned)fminf(fmaxf(rintf(o * qinv), 0.f), 65535.f);
        }
        uint4 w;
        w.x = us[0] | (us[1] << 16);
        w.y = us[2] | (us[3] << 16);
        w.z = us[4] | (us[5] << 16);
        w.w = us[6] | (us[7] << 16);
        *(uint4*)&Q[(size_t)i * NP + j0 + tx * 8] = w;
    }
}

// ---------------------------------------------------------------------------
// u16 transpose (32x32 smem tiles)
// ---------------------------------------------------------------------------
__global__ void transpose_q_kernel(const unsigned short* __restrict__ A,
                                   unsigned short* __restrict__ B) {
    __shared__ unsigned short t[32][34];
    int x = blockIdx.x * 32 + threadIdx.x;
    int y = blockIdx.y * 32 + threadIdx.y;
    #pragma unroll
    for (int j = 0; j < 32; j += 8)
        t[threadIdx.y + j][threadIdx.x] = A[(size_t)(y + j) * NP + x];
    __syncthreads();
    x = blockIdx.y * 32 + threadIdx.x;
    y = blockIdx.x * 32 + threadIdx.y;
    #pragma unroll
    for (int j = 0; j < 32; j += 8)
        B[(size_t)(y + j) * NP + x] = t[threadIdx.x][threadIdx.y + j];
}

// ---------------------------------------------------------------------------
// u16 -> float decode (exact): (0x4B000000 | u) as float == 2^23 + u
// ---------------------------------------------------------------------------
__device__ __forceinline__ float u16lo(unsigned w) {
    return __uint_as_float(__byte_perm(w, 0x4B000000u, 0x7410)) - 8388608.0f;
}
__device__ __forceinline__ float u16hi(unsigned w) {
    return __uint_as_float(__byte_perm(w, 0x4B000000u, 0x7432)) - 8388608.0f;
}

// one 16-element chunk of the online LSE, with safe negligibility skip.
__device__ __forceinline__ void chunk16q(uint4 a0, uint4 a1,
                                         const float4* __restrict__ h,
                                         float kq, float& m, float& s) {
    float4 h0 = h[0], h1 = h[1], h2 = h[64], h3 = h[65];
    float v[16];
    v[0]  = fmaf(u16lo(a0.x), kq, h0.x); v[1]  = fmaf(u16hi(a0.x), kq, h0.y);
    v[2]  = fmaf(u16lo(a0.y), kq, h0.z); v[3]  = fmaf(u16hi(a0.y), kq, h0.w);
    v[4]  = fmaf(u16lo(a0.z), kq, h1.x); v[5]  = fmaf(u16hi(a0.z), kq, h1.y);
    v[6]  = fmaf(u16lo(a0.w), kq, h1.z); v[7]  = fmaf(u16hi(a0.w), kq, h1.w);
    v[8]  = fmaf(u16lo(a1.x), kq, h2.x); v[9]  = fmaf(u16hi(a1.x), kq, h2.y);
    v[10] = fmaf(u16lo(a1.y), kq, h2.z); v[11] = fmaf(u16hi(a1.y), kq, h2.w);
    v[12] = fmaf(u16lo(a1.z), kq, h3.x); v[13] = fmaf(u16hi(a1.z), kq, h3.y);
    v[14] = fmaf(u16lo(a1.w), kq, h3.z); v[15] = fmaf(u16hi(a1.w), kq, h3.w);
    float cm = v[0];
    #pragma unroll
    for (int t = 1; t < 16; t++) cm = fmaxf(cm, v[t]);
    // skipped chunks contribute < 4096*2^-25 ~ 1.2e-4 relative in s total.
    if (__all_sync(0xffffffffu, cm < m - 25.0f)) return;
    float cs = 0.f;
    #pragma unroll
    for (int t = 0; t < 16; t++) cs += ex2(v[t] - cm);
    float nm = fmaxf(m, cm);
    s = s * ex2(m - nm) + cs * ex2(cm - nm);
    m = nm;
}

// dual-stream pipelined LSE; first segment preloaded by the caller; at the
// last segment it prefetches segment 0 for the NEXT iteration into the regs.
__device__ __forceinline__ float2 row_lse_dual_q(
        const uint4* __restrict__ QA4, const uint4* __restrict__ QB4,
        const float4* __restrict__ HA, const float4* __restrict__ HB,
        float kq, int lane,
        uint4& a0, uint4& a1, uint4& b0, uint4& b1) {
    float mA = -INFINITY, sA = 0.f;
    float mB = -INFINITY, sB = 0.f;
    #pragma unroll
    for (int seg = 0; seg < 8; seg++) {
        int sn = ((seg + 1) & 7) * 64 + lane;   // seg7 prefetches seg0 (next iter)
        uint4 na0 = QA4[sn],          na1 = QA4[sn + 32];
        uint4 nb0 = __ldcg(QB4 + sn), nb1 = __ldcg(QB4 + sn + 32);
        int sa = seg * 64 + lane;
        chunk16q(a0, a1, HA + sa * 2, kq, mA, sA);
        chunk16q(b0, b1, HB + sa * 2, kq, mB, sB);
        a0 = na0; a1 = na1; b0 = nb0; b1 = nb1;
    }
    #pragma unroll
    for (int off = 16; off; off >>= 1) {
        float om = __shfl_xor_sync(0xffffffffu, mA, off);
        float os = __shfl_xor_sync(0xffffffffu, sA, off);
        float nm = fmaxf(mA, om);
        sA = sA * ex2(mA - nm) + os * ex2(om - nm);
        mA = nm;
        float om2 = __shfl_xor_sync(0xffffffffu, mB, off);
        float os2 = __shfl_xor_sync(0xffffffffu, sB, off);
        float nm2 = fmaxf(mB, om2);
        sB = sB * ex2(mB - nm2) + os2 * ex2(om2 - nm2);
        mB = nm2;
    }
    return make_float2(mA + lg2(sA), mB + lg2(sB));
}

__device__ __forceinline__ void init_eps(float* sh_eps, int tid) {
    if (tid < 56) {
        double e = (tid < 55)
            ? exp(5.545177444479562 - 0.21072103131565253 * (double)tid)
            : 0.0025;
        sh_eps[tid] = (float)e;
    }
}

__device__ __forceinline__ void fill_bias(float* sh, const float* pot,
                                          float inv_e, int tid) {
    const float4* p4 = (const float4*)pot;
    float4* s4 = (float4*)sh;
    #pragma unroll
    for (int q = 0; q < 2; q++) {
        int j = tid + q * 512;
        float4 v = __ldcg(p4 + j);
        float4 o;
        o.x = fmaf(v.x, inv_e, NEG_LOGN) * LOG2E;
        o.y = fmaf(v.y, inv_e, NEG_LOGN) * LOG2E;
        o.z = fmaf(v.z, inv_e, NEG_LOGN) * LOG2E;
        o.w = fmaf(v.w, inv_e, NEG_LOGN) * LOG2E;
        s4[j] = o;
    }
}

// ---------------------------------------------------------------------------
// dual annealing phase on globally-quantized matrices (offset 0, shared q):
// val = -eps*ln2*lse   with arg = -(u*q)/eps*log2e + h
// ---------------------------------------------------------------------------
__global__ void __launch_bounds__(512, 2) dual_phase_kernel(
        const unsigned short* __restrict__ QA, const unsigned short* __restrict__ QB,
        float* __restrict__ bA0, float* __restrict__ bA1,
        float* __restrict__ uA0, float* __restrict__ uA1,
        float* __restrict__ bB0, float* __restrict__ bB1,
        float* __restrict__ uB0, float* __restrict__ uB1,
        float* __restrict__ outA, float* __restrict__ outB) {
    __shared__ __align__(16) float shA[NP];
    __shared__ __align__(16) float shB[NP];
    __shared__ float sh_eps[56];
    int tid = threadIdx.x, lane = tid & 31, warp = tid >> 5;
    int row = warp * NBLK + (int)blockIdx.x;
    bool active = row < NP;
    int prow = active ? row : 0;
    init_eps(sh_eps, tid);
    float qs = q_scale();
    const uint4* QA4 = (const uint4*)(QA + (size_t)prow * NP);
    const uint4* QB4 = (const uint4*)(QB + (size_t)prow * NP);
    float* bA[2] = { bA0, bA1 };
    float* uA[2] = { uA0, uA1 };
    float* bB[2] = { bB0, bB1 };
    float* uB[2] = { uB0, uB1 };
    int cur = 0;
    // preload segment 0 (both streams)
    uint4 a0 = QA4[lane],          a1 = QA4[lane + 32];
    uint4 b0 = __ldcg(QB4 + lane), b1 = __ldcg(QB4 + lane + 32);
    __syncthreads();

    for (int t = 0; t <= 57; t++) {
        int ke = (t == 0) ? 0 : (t == 57 ? 55 : t - 1);
        float e = sh_eps[ke];
        float inv_e = 1.f / e;
        float kq = -qs * inv_e * LOG2E;

        if (t == 0) {
            for (int j = tid; j < NP; j += 512) {
                shA[j] = NEG_LOGN * LOG2E;
                shB[j] = NEG_LOGN * LOG2E;
            }
        } else {
            fill_bias(shA, bA[cur], inv_e, tid);
            fill_bias(shB, bB[cur], inv_e, tid);
        }
        __syncthreads();

        float2 ls = row_lse_dual_q(QA4, QB4, (const float4*)shA,
                                   (const float4*)shB, kq, lane,
                                   a0, a1, b0, b1);

        if (lane == 0 && active) {
            float vA = -e * LN2 * ls.x;
            float vB = -e * LN2 * ls.y;
            if (t == 57) {
                outA[row] = vA;
                outB[row] = vB;
            } else if (t == 0) {
                __stcg(&uA[1][row], vA);
                __stcg(&uB[1][row], vB);
            } else {
                __stcg(&uA[cur ^ 1][row],
                       0.5f * __ldcg(&uA[cur][row]) + 0.5f * vA);
                __stcg(&uB[cur ^ 1][row],
                       0.5f * __ldcg(&uB[cur][row]) + 0.5f * vB);
            }
        }
        if (t == 0) cur = 1; else if (t < 57) cur ^= 1;
        if (t < 57) gsync();
    }
}

// ---------------------------------------------------------------------------
__global__ void loss_reduce(const float* __restrict__ fin, float* __restrict__ out, int first) {
    __shared__ float red[256];
    int tid = threadIdx.x;
    float a = 0.f;
    for (int j = tid; j < NP; j += 256)
        a += (fin[2 * NP + j] - fin[0 * NP + j]) + (fin[3 * NP + j] - fin[1 * NP + j]);
    red[tid] = a;
    __syncthreads();
    for (int sft = 128; sft; sft >>= 1) {
        if (tid < sft) red[tid] += red[tid + sft];
        __syncthreads();
    }
    if (tid == 0) {
        float v = red[0] * (1.0f / NP) * 0.25f;
        if (first) *out = v; else *out += v;
    }
}

// ---------------------------------------------------------------------------
extern "C" void kernel_launch(void* const* d_in, const int* in_sizes, int n_in,
                              void* d_out, int out_size) {
    (void)in_sizes; (void)n_in; (void)out_size;
    const float* x = (const float*)d_in[0];
    const float* y = (const float*)d_in[1];
    float* out = (float*)d_out;

    Scratch* sp = nullptr;
    cudaGetSymbolAddress((void**)&sp, S);
    float* xt  = sp->xt;  float* yt  = sp->yt;
    float* sqx = sp->sqx; float* sqy = sp->sqy;
    float* f0 = sp->f[0]; float* f1 = sp->f[1];
    float* g0 = sp->g[0]; float* g1 = sp->g[1];
    float* fin = (float*)sp->fin;

    for (int b = 0; b < 4; b++) {
        const float* xb = x + (size_t)b * 64 * NP;
        const float* yb = y + (size_t)b * 64 * NP;

        reset_max_kernel<<<1, 1>>>();
        prep_kernel<<<16, 256>>>(xb, yb, xt, yt, sqx, sqy);
        cost_quant_kernel<<<dim3(32, 32), 256>>>(xt, xt, sqx, sqx, sp->Qxx);
        cost_quant_kernel<<<dim3(32, 32), 256>>>(yt, yt, sqy, sqy, sp->Qyy);

        // fused xx+yy phase (self-coupled streams)
        dual_phase_kernel<<<NBLK, 512>>>(sp->Qxx, sp->Qyy,
                                         f0, f1, f0, f1,
                                         g0, g1, g0, g1,
                                         fin + 0 * NP, fin + 1 * NP);

        cost_quant_kernel<<<dim3(32, 32), 256>>>(xt, yt, sqx, sqy, sp->QD);
        transpose_q_kernel<<<dim3(128, 128), dim3(32, 8)>>>(sp->QD, sp->QDT);

        // xy phase (cross-coupled)
        dual_phase_kernel<<<NBLK, 512>>>(sp->QD, sp->QDT,
                                         g0, g1, f0, f1,
                                         f0, f1, g0, g1,
                                         fin + 2 * NP, fin + 3 * NP);

        loss_reduce<<<1, 256>>>(fin, out, b == 0 ? 1 : 0);
    }
}

// round 14
// speedup vs baseline: 1.2270x; 1.0645x over previous
#include <cuda_runtime.h>
#include <math.h>

#define NP 4096
#define NBLK 296
#define NEG_LOGN (-8.317766166719343f)   /* -log(4096) */
#define LOG2E 1.4426950408889634f
#define LN2   0.6931471805599453f
#define QSMEM ((4 * NP + 64) * 4)        /* 4 bias arrays + eps table */

struct __align__(16) Scratch {
    unsigned short Qxx[(size_t)NP * NP];   // 32 MB quantized
    unsigned short Qyy[(size_t)NP * NP];
    unsigned short QD [(size_t)NP * NP];
    unsigned short QDT[(size_t)NP * NP];
    float xt[NP * 64], yt[NP * 64];
    float sqx[NP], sqy[NP];
    float pots[8][NP];   // fa0 fa1 gb0 gb1 fba0 fba1 gab0 gab1
    float fin[4][NP];    // f_aa, g_bb, f_ba, g_ab (final)
};
__device__ Scratch S;

__device__ unsigned g_maxsq;   // max squared norm of the batch (float bits)

// single-instruction MUFU ops
__device__ __forceinline__ float ex2(float x) {
    float y;
    asm("ex2.approx.ftz.f32 %0, %1;" : "=f"(y) : "f"(x));
    return y;
}
__device__ __forceinline__ float lg2(float x) {
    float y;
    asm("lg2.approx.f32 %0, %1;" : "=f"(y) : "f"(x));
    return y;
}

// quantization scale from the batch max norm: C = 0.5|x-y|^2 <= 2*maxsq
__device__ __forceinline__ float q_scale() {
    float ms = fmaxf(__uint_as_float(g_maxsq), 1e-6f);
    return 2.0f * ms * (1.0f / 65535.0f);
}

// ---------------------------------------------------------------------------
// software grid barrier (NBLK blocks, 2/SM co-resident)
// ---------------------------------------------------------------------------
__device__ unsigned g_cnt;
__device__ unsigned g_gen;

__device__ __forceinline__ void gsync() {
    __threadfence();
    __syncthreads();
    if (threadIdx.x == 0) {
        volatile unsigned* vg = &g_gen;
        unsigned my = *vg;
        if (atomicAdd(&g_cnt, 1u) == NBLK - 1u) {
            g_cnt = 0u;
            __threadfence();
            *vg = my + 1u;
        } else {
            while (*vg == my) { }
        }
    }
    __syncthreads();
}

// ---------------------------------------------------------------------------
__global__ void reset_max_kernel() { g_maxsq = 0u; }

__global__ void prep_kernel(const float* __restrict__ x, const float* __restrict__ y,
                            float* __restrict__ xt, float* __restrict__ yt,
                            float* __restrict__ sqx, float* __restrict__ sqy) {
    __shared__ float red[8];
    int p = blockIdx.x * blockDim.x + threadIdx.x;
    float sx = 0.f, sy = 0.f;
    #pragma unroll 8
    for (int c = 0; c < 64; c++) {
        float vx = x[c * NP + p];
        float vy = y[c * NP + p];
        xt[p * 64 + c] = vx;
        yt[p * 64 + c] = vy;
        sx = fmaf(vx, vx, sx);
        sy = fmaf(vy, vy, sy);
    }
    sqx[p] = sx; sqy[p] = sy;
    float mx = fmaxf(sx, sy);
    #pragma unroll
    for (int o = 16; o; o >>= 1)
        mx = fmaxf(mx, __shfl_xor_sync(0xffffffffu, mx, o));
    if ((threadIdx.x & 31) == 0) red[threadIdx.x >> 5] = mx;
    __syncthreads();
    if (threadIdx.x == 0) {
        float m = red[0];
        #pragma unroll
        for (int w = 1; w < 8; w++) m = fmaxf(m, red[w]);
        atomicMax(&g_maxsq, __float_as_uint(m));
    }
}

// ---------------------------------------------------------------------------
// cost + quantize: Q[i][j] = round(0.5*|a_i - b_j|^2 / q), u16, offset 0
// ---------------------------------------------------------------------------
__global__ void cost_quant_kernel(const float* __restrict__ A, const float* __restrict__ Bm,
                                  const float* __restrict__ sqa, const float* __restrict__ sqb,
                                  unsigned short* __restrict__ Q) {
    __shared__ float As[16 * 128];
    __shared__ float Bs[16 * 128];
    int tid = threadIdx.x;
    int tx = tid & 15, ty = tid >> 4;
    int i0 = blockIdx.y * 128, j0 = blockIdx.x * 128;
    float qinv = 1.0f / q_scale();

    float acc[8][8];
    #pragma unroll
    for (int r = 0; r < 8; r++)
        #pragma unroll
        for (int c = 0; c < 8; c++) acc[r][c] = 0.f;

    for (int c0 = 0; c0 < 64; c0 += 16) {
        #pragma unroll
        for (int n = 0; n < 2; n++) {
            int idx = tid + n * 256;
            int r = idx >> 2, q = idx & 3;
            float4 va = *(const float4*)&A[(size_t)(i0 + r) * 64 + c0 + q * 4];
            As[(q * 4 + 0) * 128 + r] = va.x;
            As[(q * 4 + 1) * 128 + r] = va.y;
            As[(q * 4 + 2) * 128 + r] = va.z;
            As[(q * 4 + 3) * 128 + r] = va.w;
            float4 vb = *(const float4*)&Bm[(size_t)(j0 + r) * 64 + c0 + q * 4];
            Bs[(q * 4 + 0) * 128 + r] = vb.x;
            Bs[(q * 4 + 1) * 128 + r] = vb.y;
            Bs[(q * 4 + 2) * 128 + r] = vb.z;
            Bs[(q * 4 + 3) * 128 + r] = vb.w;
        }
        __syncthreads();
        #pragma unroll
        for (int k = 0; k < 16; k++) {
            float a[8], bb[8];
            *(float4*)&a[0]  = *(const float4*)&As[k * 128 + ty * 8];
            *(float4*)&a[4]  = *(const float4*)&As[k * 128 + ty * 8 + 4];
            *(float4*)&bb[0] = *(const float4*)&Bs[k * 128 + tx * 8];
            *(float4*)&bb[4] = *(const float4*)&Bs[k * 128 + tx * 8 + 4];
            #pragma unroll
            for (int r = 0; r < 8; r++)
                #pragma unroll
                for (int c = 0; c < 8; c++)
                    acc[r][c] = fmaf(a[r], bb[c], acc[r][c]);
        }
        __syncthreads();
    }

    float sj[8];
    #pragma unroll
    for (int c = 0; c < 8; c++) sj[c] = sqb[j0 + tx * 8 + c];

    #pragma unroll
    for (int r = 0; r < 8; r++) {
        int i = i0 + ty * 8 + r;
        float si = sqa[i];
        unsigned us[8];
        #pragma unroll
        for (int c = 0; c < 8; c++) {
            float o = 0.5f * (si + sj[c] - 2.f * acc[r][c]);
            us[c] = (unsigned)fminf(fmaxf(rintf(o * qinv), 0.f), 65535.f);
        }
        uint4 w;
        w.x = us[0] | (us[1] << 16);
        w.y = us[2] | (us[3] << 16);
        w.z = us[4] | (us[5] << 16);
        w.w = us[6] | (us[7] << 16);
        *(uint4*)&Q[(size_t)i * NP + j0 + tx * 8] = w;
    }
}

// ---------------------------------------------------------------------------
// u16 transpose (32x32 smem tiles)
// ---------------------------------------------------------------------------
__global__ void transpose_q_kernel(const unsigned short* __restrict__ A,
                                   unsigned short* __restrict__ B) {
    __shared__ unsigned short t[32][34];
    int x = blockIdx.x * 32 + threadIdx.x;
    int y = blockIdx.y * 32 + threadIdx.y;
    #pragma unroll
    for (int j = 0; j < 32; j += 8)
        t[threadIdx.y + j][threadIdx.x] = A[(size_t)(y + j) * NP + x];
    __syncthreads();
    x = blockIdx.y * 32 + threadIdx.x;
    y = blockIdx.x * 32 + threadIdx.y;
    #pragma unroll
    for (int j = 0; j < 32; j += 8)
        B[(size_t)(y + j) * NP + x] = t[threadIdx.x][threadIdx.y + j];
}

// ---------------------------------------------------------------------------
// u16 -> float decode (exact): (0x4B000000 | u) as float == 2^23 + u
// ---------------------------------------------------------------------------
__device__ __forceinline__ float u16lo(unsigned w) {
    return __uint_as_float(__byte_perm(w, 0x4B000000u, 0x7410)) - 8388608.0f;
}
__device__ __forceinline__ float u16hi(unsigned w) {
    return __uint_as_float(__byte_perm(w, 0x4B000000u, 0x7432)) - 8388608.0f;
}

// single-ex2 (m,s) merge: one MUFU instead of two
__device__ __forceinline__ void merge_ms(float& m, float& s, float om, float os) {
    float d = om - m;
    float e1 = ex2(-fabsf(d));
    bool gt = d > 0.f;
    float sn = gt ? fmaf(s, e1, os) : fmaf(os, e1, s);
    if (gt) m = om;
    s = sn;
}

// one 16-element chunk of the online LSE, with safe negligibility skip
__device__ __forceinline__ void chunk16q(uint4 a0, uint4 a1,
                                         const float4* __restrict__ h,
                                         float kq, float& m, float& s) {
    float4 h0 = h[0], h1 = h[1], h2 = h[64], h3 = h[65];
    float v[16];
    v[0]  = fmaf(u16lo(a0.x), kq, h0.x); v[1]  = fmaf(u16hi(a0.x), kq, h0.y);
    v[2]  = fmaf(u16lo(a0.y), kq, h0.z); v[3]  = fmaf(u16hi(a0.y), kq, h0.w);
    v[4]  = fmaf(u16lo(a0.z), kq, h1.x); v[5]  = fmaf(u16hi(a0.z), kq, h1.y);
    v[6]  = fmaf(u16lo(a0.w), kq, h1.z); v[7]  = fmaf(u16hi(a0.w), kq, h1.w);
    v[8]  = fmaf(u16lo(a1.x), kq, h2.x); v[9]  = fmaf(u16hi(a1.x), kq, h2.y);
    v[10] = fmaf(u16lo(a1.y), kq, h2.z); v[11] = fmaf(u16hi(a1.y), kq, h2.w);
    v[12] = fmaf(u16lo(a1.z), kq, h3.x); v[13] = fmaf(u16hi(a1.z), kq, h3.y);
    v[14] = fmaf(u16lo(a1.w), kq, h3.z); v[15] = fmaf(u16hi(a1.w), kq, h3.w);
    float cm = v[0];
    #pragma unroll
    for (int t = 1; t < 16; t++) cm = fmaxf(cm, v[t]);
    // skipped chunks contribute < 4096*2^-25 ~ 1.2e-4 relative in s total
    if (__all_sync(0xffffffffu, cm < m - 25.0f)) return;
    float cs = 0.f;
    #pragma unroll
    for (int t = 0; t < 16; t++) cs += ex2(v[t] - cm);
    merge_ms(m, s, cm, cs);
}

__device__ __forceinline__ void init_eps(float* sh_eps, int tid) {
    if (tid < 56) {
        double e = (tid < 55)
            ? exp(5.545177444479562 - 0.21072103131565253 * (double)tid)
            : 0.0025;
        sh_eps[tid] = (float)e;
    }
}

__device__ __forceinline__ void fill_bias(float* sh, const float* pot,
                                          float inv_e, int tid) {
    const float4* p4 = (const float4*)pot;
    float4* s4 = (float4*)sh;
    #pragma unroll
    for (int q = 0; q < 2; q++) {
        int j = tid + q * 512;
        float4 v = __ldcg(p4 + j);
        float4 o;
        o.x = fmaf(v.x, inv_e, NEG_LOGN) * LOG2E;
        o.y = fmaf(v.y, inv_e, NEG_LOGN) * LOG2E;
        o.z = fmaf(v.z, inv_e, NEG_LOGN) * LOG2E;
        o.w = fmaf(v.w, inv_e, NEG_LOGN) * LOG2E;
        s4[j] = o;
    }
}

// ---------------------------------------------------------------------------
// quad annealing phase: all four Sinkhorn recursions in one persistent kernel.
//   A: Qxx -> f_aa (self)   B: Qyy -> g_bb (self)
//   C: QD  -> f_ba (biased by g_ab)   D: QDT -> g_ab (biased by f_ba)
// pots layout [8][NP]: fa0 fa1 gb0 gb1 fba0 fba1 gab0 gab1
// ---------------------------------------------------------------------------
__global__ void __launch_bounds__(512, 2) quad_phase_kernel(
        const unsigned short* __restrict__ QA, const unsigned short* __restrict__ QB,
        const unsigned short* __restrict__ QC, const unsigned short* __restrict__ QDm,
        float* __restrict__ pots, float* __restrict__ fin) {
    extern __shared__ __align__(16) float sm[];
    float* shA = sm;
    float* shB = sm + NP;
    float* shC = sm + 2 * NP;
    float* shD = sm + 3 * NP;
    float* sh_eps = sm + 4 * NP;

    int tid = threadIdx.x, lane = tid & 31, warp = tid >> 5;
    int row = warp * NBLK + (int)blockIdx.x;
    bool active = row < NP;
    int prow = active ? row : 0;
    init_eps(sh_eps, tid);
    float qs = q_scale();
    const uint4* QA4 = (const uint4*)(QA  + (size_t)prow * NP);
    const uint4* QB4 = (const uint4*)(QB  + (size_t)prow * NP);
    const uint4* QC4 = (const uint4*)(QC  + (size_t)prow * NP);
    const uint4* QD4 = (const uint4*)(QDm + (size_t)prow * NP);
    int cur = 0;
    __syncthreads();

    for (int t = 0; t <= 57; t++) {
        int ke = (t == 0) ? 0 : (t == 57 ? 55 : t - 1);
        float e = sh_eps[ke];
        float inv_e = 1.f / e;
        float kq = -qs * inv_e * LOG2E;

        if (t == 0) {
            for (int j = tid; j < 4 * NP; j += 512)
                sm[j] = NEG_LOGN * LOG2E;
        } else {
            fill_bias(shA, pots + (0 + cur) * NP, inv_e, tid);   // fa
            fill_bias(shB, pots + (2 + cur) * NP, inv_e, tid);   // gb
            fill_bias(shC, pots + (6 + cur) * NP, inv_e, tid);   // gab biases f_ba
            fill_bias(shD, pots + (4 + cur) * NP, inv_e, tid);   // fba biases g_ab
        }
        __syncthreads();

        float mA = -INFINITY, sA = 0.f;
        float mB = -INFINITY, sB = 0.f;
        float mC = -INFINITY, sC = 0.f;
        float mD = -INFINITY, sD = 0.f;
        const float4* HA = (const float4*)shA;
        const float4* HB = (const float4*)shB;
        const float4* HC = (const float4*)shC;
        const float4* HD = (const float4*)shD;
        #pragma unroll 2
        for (int seg = 0; seg < 8; seg++) {
            int sa = seg * 64 + lane;
            uint4 x0, x1;
            x0 = __ldcg(QA4 + sa); x1 = __ldcg(QA4 + sa + 32);
            chunk16q(x0, x1, HA + sa * 2, kq, mA, sA);
            x0 = __ldcg(QB4 + sa); x1 = __ldcg(QB4 + sa + 32);
            chunk16q(x0, x1, HB + sa * 2, kq, mB, sB);
            x0 = __ldcg(QC4 + sa); x1 = __ldcg(QC4 + sa + 32);
            chunk16q(x0, x1, HC + sa * 2, kq, mC, sC);
            x0 = __ldcg(QD4 + sa); x1 = __ldcg(QD4 + sa + 32);
            chunk16q(x0, x1, HD + sa * 2, kq, mD, sD);
        }
        #pragma unroll
        for (int off = 16; off; off >>= 1) {
            merge_ms(mA, sA, __shfl_xor_sync(0xffffffffu, mA, off),
                             __shfl_xor_sync(0xffffffffu, sA, off));
            merge_ms(mB, sB, __shfl_xor_sync(0xffffffffu, mB, off),
                             __shfl_xor_sync(0xffffffffu, sB, off));
            merge_ms(mC, sC, __shfl_xor_sync(0xffffffffu, mC, off),
                             __shfl_xor_sync(0xffffffffu, sC, off));
            merge_ms(mD, sD, __shfl_xor_sync(0xffffffffu, mD, off),
                             __shfl_xor_sync(0xffffffffu, sD, off));
        }

        if (lane == 0 && active) {
            float nel = -e * LN2;
            float vA = nel * (mA + lg2(sA));
            float vB = nel * (mB + lg2(sB));
            float vC = nel * (mC + lg2(sC));
            float vD = nel * (mD + lg2(sD));
            if (t == 57) {
                fin[0 * NP + row] = vA;
                fin[1 * NP + row] = vB;
                fin[2 * NP + row] = vC;
                fin[3 * NP + row] = vD;
            } else if (t == 0) {
                __stcg(&pots[(0 + 1) * NP + row], vA);
                __stcg(&pots[(2 + 1) * NP + row], vB);
                __stcg(&pots[(4 + 1) * NP + row], vC);
                __stcg(&pots[(6 + 1) * NP + row], vD);
            } else {
                int nx = cur ^ 1;
                __stcg(&pots[(0 + nx) * NP + row],
                       0.5f * __ldcg(&pots[(0 + cur) * NP + row]) + 0.5f * vA);
                __stcg(&pots[(2 + nx) * NP + row],
                       0.5f * __ldcg(&pots[(2 + cur) * NP + row]) + 0.5f * vB);
                __stcg(&pots[(4 + nx) * NP + row],
                       0.5f * __ldcg(&pots[(4 + cur) * NP + row]) + 0.5f * vC);
                __stcg(&pots[(6 + nx) * NP + row],
                       0.5f * __ldcg(&pots[(6 + cur) * NP + row]) + 0.5f * vD);
            }
        }
        if (t == 0) cur = 1; else if (t < 57) cur ^= 1;
        if (t < 57) gsync();
    }
}

// ---------------------------------------------------------------------------
__global__ void loss_reduce(const float* __restrict__ fin, float* __restrict__ out, int first) {
    __shared__ float red[256];
    int tid = threadIdx.x;
    float a = 0.f;
    for (int j = tid; j < NP; j += 256)
        a += (fin[2 * NP + j] - fin[0 * NP + j]) + (fin[3 * NP + j] - fin[1 * NP + j]);
    red[tid] = a;
    __syncthreads();
    for (int sft = 128; sft; sft >>= 1) {
        if (tid < sft) red[tid] += red[tid + sft];
        __syncthreads();
    }
    if (tid == 0) {
        float v = red[0] * (1.0f / NP) * 0.25f;
        if (first) *out = v; else *out += v;
    }
}

// ---------------------------------------------------------------------------
extern "C" void kernel_launch(void* const* d_in, const int* in_sizes, int n_in,
                              void* d_out, int out_size) {
    (void)in_sizes; (void)n_in; (void)out_size;
    const float* x = (const float*)d_in[0];
    const float* y = (const float*)d_in[1];
    float* out = (float*)d_out;

    Scratch* sp = nullptr;
    cudaGetSymbolAddress((void**)&sp, S);
    float* xt  = sp->xt;  float* yt  = sp->yt;
    float* sqx = sp->sqx; float* sqy = sp->sqy;
    float* pots = (float*)sp->pots;
    float* fin  = (float*)sp->fin;

    // opt-in 66 KB dynamic smem; 2 blocks/SM (132 KB < 228 KB) keeps the
    // grid-barrier co-residency invariant.
    cudaFuncSetAttribute(quad_phase_kernel,
                         cudaFuncAttributeMaxDynamicSharedMemorySize, QSMEM);
    cudaFuncSetAttribute(quad_phase_kernel,
                         cudaFuncAttributePreferredSharedMemoryCarveout, 100);

    for (int b = 0; b < 4; b++) {
        const float* xb = x + (size_t)b * 64 * NP;
        const float* yb = y + (size_t)b * 64 * NP;

        reset_max_kernel<<<1, 1>>>();
        prep_kernel<<<16, 256>>>(xb, yb, xt, yt, sqx, sqy);
        cost_quant_kernel<<<dim3(32, 32), 256>>>(xt, xt, sqx, sqx, sp->Qxx);
        cost_quant_kernel<<<dim3(32, 32), 256>>>(yt, yt, sqy, sqy, sp->Qyy);
        cost_quant_kernel<<<dim3(32, 32), 256>>>(xt, yt, sqx, sqy, sp->QD);
        transpose_q_kernel<<<dim3(128, 128), dim3(32, 8)>>>(sp->QD, sp->QDT);

        quad_phase_kernel<<<NBLK, 512, QSMEM>>>(sp->Qxx, sp->Qyy,
                                                sp->QD, sp->QDT, pots, fin);

        loss_reduce<<<1, 256>>>(fin, out, b == 0 ? 1 : 0);
    }
}